// round 13
// baseline (speedup 1.0000x reference)
#include <cuda_runtime.h>

#define Bn 64
#define Cn 128
#define Ln 400
#define Hn 8
#define Kn 7
#define CLn (Cn*Ln)            // 51200
#define BCL (Bn*Cn*Ln)         // 3276800
#define EPSf 1e-5f
#define LT64 64
#define NLT64 7
#define LT32 32
#define NLT32 13
#define QSCALE 0.08838834764831845f

// ---------------- scratch ----------------
__device__ float g_bufA[BCL];
__device__ float g_bufB[BCL];
__device__ float g_scr[BCL];     // attention output (B,C,L)
__device__ float g_q[BCL];       // (B,H,L,DK)
__device__ float g_k[BCL];
__device__ float g_v[BCL];
__device__ float g_partA[Bn*64*2];
__device__ float g_partB[Bn*64*2];
__device__ float4 g_wfrag[9*4096]; // mma A-fragments: [m][w(8)][k(16)][lane(32)]
__device__ float g_bqs[Cn];
__device__ float2 g_ln2[CLn];

// ---------------- helpers ----------------
typedef unsigned long long u64;
__device__ __forceinline__ float to_tf32(float x){
    unsigned u; asm("cvt.rna.tf32.f32 %0, %1;" : "=r"(u) : "f"(x));
    return __uint_as_float(u);
}
__device__ __forceinline__ void mma_tf32(float* c, float4 a, float b0, float b1){
    asm volatile("mma.sync.aligned.m16n8k8.row.col.f32.tf32.tf32.f32 "
        "{%0,%1,%2,%3}, {%4,%5,%6,%7}, {%8,%9}, {%0,%1,%2,%3};"
        : "+f"(c[0]), "+f"(c[1]), "+f"(c[2]), "+f"(c[3])
        : "r"(__float_as_uint(a.x)), "r"(__float_as_uint(a.y)),
          "r"(__float_as_uint(a.z)), "r"(__float_as_uint(a.w)),
          "r"(__float_as_uint(b0)), "r"(__float_as_uint(b1)));
}

__device__ __forceinline__ void block_reduce2(float s, float ss, float* out2, float* red){
    #pragma unroll
    for (int o = 16; o > 0; o >>= 1){
        s  += __shfl_down_sync(0xffffffffu, s,  o);
        ss += __shfl_down_sync(0xffffffffu, ss, o);
    }
    int w = threadIdx.x >> 5;
    if ((threadIdx.x & 31) == 0){ red[w*2] = s; red[w*2+1] = ss; }
    __syncthreads();
    if (threadIdx.x == 0){
        float a = 0.f, b = 0.f;
        int nw = blockDim.x >> 5;
        for (int i = 0; i < nw; i++){ a += red[i*2]; b += red[i*2+1]; }
        out2[0] = a; out2[1] = b;
    }
}

__device__ __forceinline__ void stats_from_parts(const float* partIn, int b, int nparts, float* red){
    if (threadIdx.x < 32){
        float s = 0.f, ss = 0.f;
        for (int i = threadIdx.x; i < nparts; i += 32){
            s  += partIn[(b*64+i)*2];
            ss += partIn[(b*64+i)*2+1];
        }
        #pragma unroll
        for (int o = 16; o > 0; o >>= 1){
            s  += __shfl_down_sync(0xffffffffu, s,  o);
            ss += __shfl_down_sync(0xffffffffu, ss, o);
        }
        if (threadIdx.x == 0){
            float mu  = s / (float)CLn;
            float var = ss / (float)CLn - mu*mu;
            red[0] = mu;
            red[1] = rsqrtf(var + EPSf);
        }
    }
}

// ---------------- prep ----------------
__global__ __launch_bounds__(256) void k_prep(
        const float* __restrict__ pw, const float* __restrict__ wq,
        const float* __restrict__ wk, const float* __restrict__ wv,
        const float* __restrict__ wo, const float* __restrict__ fcw,
        const float* __restrict__ bq,
        const float* __restrict__ lng, const float* __restrict__ lnb){
    int idx = blockIdx.x*256 + threadIdx.x;
    if (idx < 9*4096){
        int m = idx >> 12;
        int rest = idx & 4095;
        int w = rest >> 9;
        int k = (rest >> 5) & 15;
        int lane = rest & 31;
        int r = lane >> 2, cq = lane & 3;
        const float* src = (m < 4) ? (pw + m*Cn*Cn) :
                           (m == 4) ? wq : (m == 5) ? wk : (m == 6) ? wv :
                           (m == 7) ? wo : fcw;
        float sc = (m == 4) ? QSCALE : 1.f;
        int mo = w*16, c0 = k*8;
        float a0 = to_tf32(src[(mo + r    )*Cn + c0 + cq    ] * sc);
        float a1 = to_tf32(src[(mo + r + 8)*Cn + c0 + cq    ] * sc);
        float a2 = to_tf32(src[(mo + r    )*Cn + c0 + cq + 4] * sc);
        float a3 = to_tf32(src[(mo + r + 8)*Cn + c0 + cq + 4] * sc);
        g_wfrag[idx] = make_float4(a0, a1, a2, a3);
    }
    if (idx < CLn) g_ln2[idx] = make_float2(lng[idx], lnb[idx]);
    if (idx < Cn) g_bqs[idx] = bq[idx] * QSCALE;
}

// ---------------- x + positional encoding ----------------
__global__ __launch_bounds__(256) void k_pos(const float* __restrict__ x){
    __shared__ float fr[Cn], phs[Cn];
    __shared__ float red[16];
    int tid = threadIdx.x;
    if (tid < Cn){
        int c = tid;
        if ((c & 1) == 0){ fr[c] =  powf(10000.f, -(float)c/128.f);       phs[c] = 0.f; }
        else             { fr[c] = -powf(10000.f, (1.f-(float)c)/128.f);  phs[c] = 1.5707963267948966f; }
    }
    __syncthreads();
    int b  = blockIdx.x;
    int i4 = blockIdx.y * 256 + tid;
    float4 xv = ((const float4*)x)[b*(CLn/4) + i4];
    int e0 = i4 * 4;
    int c  = e0 / Ln;
    int l  = e0 - c * Ln;
    float fc = fr[c], ph = phs[c];
    float v0 = xv.x + sinf((float)(l+0)*fc + ph);
    float v1 = xv.y + sinf((float)(l+1)*fc + ph);
    float v2 = xv.z + sinf((float)(l+2)*fc + ph);
    float v3 = xv.w + sinf((float)(l+3)*fc + ph);
    ((float4*)g_bufA)[b*(CLn/4) + i4] = make_float4(v0, v1, v2, v3);
    float s  = v0 + v1 + v2 + v3;
    float ss = v0*v0 + v1*v1 + v2*v2 + v3*v3;
    block_reduce2(s, ss, &g_partA[(b*64 + blockIdx.y)*2], red);
}

// ===== GEMM mainloop, 8 n-tiles (64 cols), pitch P (P mod 32 == 8 -> conflict-free) =====
#define GEMM_MMA8(WFp, XS, P)                                                   \
    int lane = tid & 31, w = tid >> 5;                                          \
    int r = lane >> 2, cq = lane & 3;                                           \
    float acc[8][4];                                                            \
    _Pragma("unroll")                                                           \
    for (int nt = 0; nt < 8; nt++){                                             \
        acc[nt][0] = 0.f; acc[nt][1] = 0.f; acc[nt][2] = 0.f; acc[nt][3] = 0.f; \
    }                                                                           \
    {                                                                           \
        const float4* af = (WFp) + w*512 + lane;                                \
        _Pragma("unroll")                                                       \
        for (int k = 0; k < 16; k++){                                           \
            float4 a = af[k*32];                                                \
            const float* xb = (XS) + (k*8 + cq)*(P) + r;                        \
            _Pragma("unroll")                                                   \
            for (int nt = 0; nt < 8; nt++){                                     \
                mma_tf32(acc[nt], a, xb[nt*8], xb[4*(P) + nt*8]);               \
            }                                                                   \
        }                                                                       \
    }

// ---------------- fused conv layer ----------------
// grid (B, NLT64), block 256
// smem: XsmH [c][70] pitch 72 (x halo; depthwise writes y[c][l] to index l+6 in-place)
#define CONV_SMEM_F (9216 + 1024 + 128 + 16)
__global__ __launch_bounds__(256, 4) void k_conv(
        const float* __restrict__ in, float* __restrict__ out,
        const float4* __restrict__ Wf,
        const float* __restrict__ dw, const float* __restrict__ db,
        const float* __restrict__ pb,
        const float* __restrict__ partIn, float* __restrict__ partOut, int nparts){
    extern __shared__ float sm[];
    float* XsmH = sm;                  // [c][70] pitch 72 ; y aliased at +6
    float* Dw   = sm + 9216;
    float* Db   = Dw + 1024;
    float* red  = Db + 128;
    int b = blockIdx.x, lt = blockIdx.y, tid = threadIdx.x;
    int l0 = lt * LT64;

    stats_from_parts(partIn, b, nparts, red);
    for (int idx = tid; idx < Cn*Kn; idx += 256)
        Dw[(idx/7)*8 + (idx - (idx/7)*7)] = dw[idx];
    if (tid < Cn) Db[tid] = db[tid];
    __syncthreads();
    float mu = red[0], rs = red[1];
    for (int idx = tid; idx < Cn*70; idx += 256){
        int c = idx / 70, j = idx - c*70;
        int gl = l0 - 3 + j;
        float v = 0.f;
        if (gl >= 0 && gl < Ln){
            float2 gb = g_ln2[c*Ln + gl];
            float a = rs*gb.x;
            v = fmaf(in[(b*Cn + c)*Ln + gl], a, fmaf(-mu, a, gb.y));
        }
        XsmH[c*72 + j] = v;
    }
    __syncthreads();
    // depthwise in-place: y[c][l] -> index l+6 (the x cell read in the same iteration)
    {
        int c  = tid >> 1;
        int lb = (tid & 1) * 32;
        float* xr = XsmH + c*72 + lb;
        float d0 = Dw[c*8+0], d1 = Dw[c*8+1], d2 = Dw[c*8+2], d3 = Dw[c*8+3];
        float d4 = Dw[c*8+4], d5 = Dw[c*8+5], d6 = Dw[c*8+6];
        float bias = Db[c];
        float w0 = xr[0], w1 = xr[1], w2 = xr[2], w3 = xr[3], w4 = xr[4], w5 = xr[5];
        __syncwarp();   // all preloads (x[lb..lb+5]) before any in-place writes
        #pragma unroll
        for (int l = 0; l < 32; l++){
            float w6 = xr[l + 6];
            float a = bias;
            a = fmaf(w0, d0, a); a = fmaf(w1, d1, a); a = fmaf(w2, d2, a);
            a = fmaf(w3, d3, a); a = fmaf(w4, d4, a); a = fmaf(w5, d5, a);
            a = fmaf(w6, d6, a);
            xr[l + 6] = to_tf32(a);          // overwrite the cell just read
            w0 = w1; w1 = w2; w2 = w3; w3 = w4; w4 = w5; w5 = w6;
        }
    }
    __syncthreads();

    GEMM_MMA8(Wf, XsmH + 6, 72)

    int mo = w*16;
    float s = 0.f, ss = 0.f;
    #pragma unroll
    for (int nt = 0; nt < 8; nt++){
        int col = l0 + nt*8 + 2*cq;
        if (col < Ln){
            int o1 = mo + r, o2 = o1 + 8;
            float b1v = pb[o1], b2v = pb[o2];
            float z0 = acc[nt][0] + b1v, z1 = acc[nt][1] + b1v;
            float z2 = acc[nt][2] + b2v, z3 = acc[nt][3] + b2v;
            z0 = z0 > 0.f ? z0 : 0.f;  z1 = z1 > 0.f ? z1 : 0.f;
            z2 = z2 > 0.f ? z2 : 0.f;  z3 = z3 > 0.f ? z3 : 0.f;
            float2 r1 = *(const float2*)&in[(b*Cn + o1)*Ln + col];
            float2 r2 = *(const float2*)&in[(b*Cn + o2)*Ln + col];
            float v0 = r1.x + z0, v1 = r1.y + z1;
            float v2 = r2.x + z2, v3 = r2.y + z3;
            *(float2*)&out[(b*Cn + o1)*Ln + col] = make_float2(v0, v1);
            *(float2*)&out[(b*Cn + o2)*Ln + col] = make_float2(v2, v3);
            s  += v0 + v1 + v2 + v3;
            ss += v0*v0 + v1*v1 + v2*v2 + v3*v3;
        }
    }
    block_reduce2(s, ss, &partOut[(b*64 + lt)*2], red);
}

// ---------------- generic matmul ----------------
// grid (B, NLT64), block 256
#define MM_SMEM_F (9216 + 16)
template<bool LN, bool RELU, bool STATS>
__global__ __launch_bounds__(256, 4) void k_mm(
        const float* __restrict__ in, const float* resid, float* __restrict__ out,
        const float4* __restrict__ Wf, const float* __restrict__ bias,
        const float* __restrict__ partIn, float* __restrict__ partOut, int nparts){
    extern __shared__ float sm[];
    float* Xsm = sm;                 // [c][64] pitch 72
    float* red = sm + 9216;
    int b = blockIdx.x, lt = blockIdx.y, tid = threadIdx.x;
    int l0 = lt * LT64;
    if (LN) stats_from_parts(partIn, b, nparts, red);
    __syncthreads();
    float mu = 0.f, rs = 1.f;
    if (LN){ mu = red[0]; rs = red[1]; }
    for (int idx = tid; idx < Cn*LT64; idx += 256){
        int c = idx >> 6, j = idx & 63;
        int gl = l0 + j;
        float v = 0.f;
        if (gl < Ln){
            v = in[(b*Cn + c)*Ln + gl];
            if (LN){
                float2 gb = g_ln2[c*Ln + gl];
                float a = rs*gb.x;
                v = fmaf(v, a, fmaf(-mu, a, gb.y));
            }
        }
        Xsm[c*72 + j] = to_tf32(v);
    }
    __syncthreads();

    GEMM_MMA8(Wf, Xsm, 72)

    int mo = w*16;
    float s = 0.f, ss = 0.f;
    #pragma unroll
    for (int nt = 0; nt < 8; nt++){
        int col = l0 + nt*8 + 2*cq;
        if (col < Ln){
            int o1 = mo + r, o2 = o1 + 8;
            float b1v = bias[o1], b2v = bias[o2];
            float z0 = acc[nt][0] + b1v, z1 = acc[nt][1] + b1v;
            float z2 = acc[nt][2] + b2v, z3 = acc[nt][3] + b2v;
            if (RELU){
                z0 = z0 > 0.f ? z0 : 0.f;  z1 = z1 > 0.f ? z1 : 0.f;
                z2 = z2 > 0.f ? z2 : 0.f;  z3 = z3 > 0.f ? z3 : 0.f;
            }
            float2 r1 = *(const float2*)&resid[(b*Cn + o1)*Ln + col];
            float2 r2 = *(const float2*)&resid[(b*Cn + o2)*Ln + col];
            float v0 = r1.x + z0, v1 = r1.y + z1;
            float v2 = r2.x + z2, v3 = r2.y + z3;
            *(float2*)&out[(b*Cn + o1)*Ln + col] = make_float2(v0, v1);
            *(float2*)&out[(b*Cn + o2)*Ln + col] = make_float2(v2, v3);
            if (STATS){
                s  += v0 + v1 + v2 + v3;
                ss += v0*v0 + v1*v1 + v2*v2 + v3*v3;
            }
        }
    }
    if (STATS) block_reduce2(s, ss, &partOut[(b*64 + lt)*2], red);
}

// ---------------- merged QKV (stage X once, 3 A-streams) ----------------
// grid (B, NLT32), block 256 ; X [c][32] pitch 40
#define QKV_SMEM_F (5120 + 16)
__global__ __launch_bounds__(256, 3) void k_qkv(
        const float* __restrict__ in,
        const float* __restrict__ bq_s, const float* __restrict__ bk,
        const float* __restrict__ bv,
        const float* __restrict__ partIn, int nparts){
    extern __shared__ float sm[];
    float* Xsm = sm;
    float* red = sm + 5120;
    int b = blockIdx.x, lt = blockIdx.y, tid = threadIdx.x;
    int l0 = lt * LT32;
    stats_from_parts(partIn, b, nparts, red);
    __syncthreads();
    float mu = red[0], rs = red[1];
    for (int idx = tid; idx < Cn*LT32; idx += 256){
        int c = idx >> 5, j = idx & 31;
        int gl = l0 + j;
        float v = 0.f;
        if (gl < Ln){
            float2 gb = g_ln2[c*Ln + gl];
            float a = rs*gb.x;
            v = fmaf(in[(b*Cn + c)*Ln + gl], a, fmaf(-mu, a, gb.y));
        }
        Xsm[c*40 + j] = to_tf32(v);
    }
    __syncthreads();

    int lane = tid & 31, w = tid >> 5;
    int r = lane >> 2, cq = lane & 3;
    float acc[3][4][4];
    #pragma unroll
    for (int m = 0; m < 3; m++)
        #pragma unroll
        for (int nt = 0; nt < 4; nt++){
            acc[m][nt][0] = 0.f; acc[m][nt][1] = 0.f;
            acc[m][nt][2] = 0.f; acc[m][nt][3] = 0.f;
        }
    {
        const float4* af0 = g_wfrag + 4*4096 + w*512 + lane;
        const float4* af1 = af0 + 4096;
        const float4* af2 = af1 + 4096;
        #pragma unroll
        for (int k = 0; k < 16; k++){
            float4 aq = af0[k*32];
            float4 ak = af1[k*32];
            float4 av = af2[k*32];
            const float* xb = Xsm + (k*8 + cq)*40 + r;
            #pragma unroll
            for (int nt = 0; nt < 4; nt++){
                float b0 = xb[nt*8];
                float b1 = xb[4*40 + nt*8];
                mma_tf32(acc[0][nt], aq, b0, b1);
                mma_tf32(acc[1][nt], ak, b0, b1);
                mma_tf32(acc[2][nt], av, b0, b1);
            }
        }
    }

    int o1 = w*16 + r, o2 = o1 + 8;
    #pragma unroll
    for (int m = 0; m < 3; m++){
        const float* bias = (m == 0) ? bq_s : (m == 1) ? bk : bv;
        float* outp       = (m == 0) ? g_q  : (m == 1) ? g_k : g_v;
        float b1v = bias[o1], b2v = bias[o2];
        #pragma unroll
        for (int nt = 0; nt < 4; nt++){
            int col = l0 + nt*8 + 2*cq;
            if (col < Ln){
                float* p = outp + ((size_t)(b*Hn + w)*Ln + col)*16;
                p[r]          = acc[m][nt][0] + b1v;
                p[16 + r]     = acc[m][nt][1] + b1v;
                p[r + 8]      = acc[m][nt][2] + b2v;
                p[16 + r + 8] = acc[m][nt][3] + b2v;
            }
        }
    }
}

// ---------------- attention: flash-style tf32 mma ----------------
#define ATTN_K_P 20
#define ATTN_V_P 24
#define ATTN_P_P 44
#define ATTN_SMEM_F (Ln*ATTN_K_P + Ln*ATTN_V_P + Ln + 8*16*ATTN_P_P)
__global__ __launch_bounds__(256, 2) void k_attn(const float* __restrict__ mask){
    extern __shared__ float sm[];
    float* Ksm = sm;                                  // pitch 20
    float* Vsm = sm + Ln*ATTN_K_P;                    // pitch 24
    float* Msm = Vsm + Ln*ATTN_V_P;
    float* Pall = Msm + Ln;
    int bh = blockIdx.x;
    int b = bh >> 3, h = bh & 7;
    int tid = threadIdx.x;
    {
        const float4* kp = (const float4*)(g_k + (size_t)bh*Ln*16);
        const float4* vp = (const float4*)(g_v + (size_t)bh*Ln*16);
        for (int i = tid; i < Ln*4; i += 256){
            int row = i >> 2, q = i & 3;
            float4 kv = kp[i];
            kv.x = to_tf32(kv.x); kv.y = to_tf32(kv.y);
            kv.z = to_tf32(kv.z); kv.w = to_tf32(kv.w);
            *(float4*)(Ksm + row*ATTN_K_P + q*4) = kv;
            float4 vv = vp[i];
            vv.x = to_tf32(vv.x); vv.y = to_tf32(vv.y);
            vv.z = to_tf32(vv.z); vv.w = to_tf32(vv.w);
            *(float4*)(Vsm + row*ATTN_V_P + q*4) = vv;
        }
        for (int i = tid; i < Ln; i += 256) Msm[i] = mask[b*Ln + i];
    }
    __syncthreads();

    int lane = tid & 31, w = tid >> 5;
    int r = lane >> 2, cq = lane & 3;
    float* Pw = Pall + w*16*ATTN_P_P;
    const float* Qbase = g_q + (size_t)bh*Ln*16;
    size_t obase = ((size_t)b*Cn + h*16)*Ln;

    for (int mt = w; mt < 25; mt += 8){
        int mo = mt*16;
        float4 qf0, qf1;
        qf0.x = to_tf32(Qbase[(mo + r    )*16 + cq    ]);
        qf0.y = to_tf32(Qbase[(mo + r + 8)*16 + cq    ]);
        qf0.z = to_tf32(Qbase[(mo + r    )*16 + cq + 4]);
        qf0.w = to_tf32(Qbase[(mo + r + 8)*16 + cq + 4]);
        qf1.x = to_tf32(Qbase[(mo + r    )*16 + 8 + cq    ]);
        qf1.y = to_tf32(Qbase[(mo + r + 8)*16 + 8 + cq    ]);
        qf1.z = to_tf32(Qbase[(mo + r    )*16 + 8 + cq + 4]);
        qf1.w = to_tf32(Qbase[(mo + r + 8)*16 + 8 + cq + 4]);

        float m0 = -3.0e38f, m1 = -3.0e38f, den0 = 0.f, den1 = 0.f;
        float oa[2][4];
        oa[0][0]=oa[0][1]=oa[0][2]=oa[0][3]=0.f;
        oa[1][0]=oa[1][1]=oa[1][2]=oa[1][3]=0.f;

        for (int kc = 0; kc < Ln; kc += 40){
            float sc[5][4];
            #pragma unroll
            for (int st = 0; st < 5; st++){
                sc[st][0]=0.f; sc[st][1]=0.f; sc[st][2]=0.f; sc[st][3]=0.f;
                const float* kb = Ksm + (kc + st*8 + r)*ATTN_K_P + cq;
                mma_tf32(sc[st], qf0, kb[0], kb[4]);
                mma_tf32(sc[st], qf1, kb[8], kb[12]);
            }
            #pragma unroll
            for (int st = 0; st < 5; st++){
                float2 mk = *(const float2*)(Msm + kc + st*8 + 2*cq);
                float a0 = (1.f - mk.x)*(-1e30f), a1 = (1.f - mk.y)*(-1e30f);
                sc[st][0] = sc[st][0]*mk.x + a0;
                sc[st][1] = sc[st][1]*mk.y + a1;
                sc[st][2] = sc[st][2]*mk.x + a0;
                sc[st][3] = sc[st][3]*mk.y + a1;
            }
            float cm0 = -3.0e38f, cm1 = -3.0e38f;
            #pragma unroll
            for (int st = 0; st < 5; st++){
                cm0 = fmaxf(cm0, fmaxf(sc[st][0], sc[st][1]));
                cm1 = fmaxf(cm1, fmaxf(sc[st][2], sc[st][3]));
            }
            cm0 = fmaxf(cm0, __shfl_xor_sync(0xffffffffu, cm0, 1));
            cm0 = fmaxf(cm0, __shfl_xor_sync(0xffffffffu, cm0, 2));
            cm1 = fmaxf(cm1, __shfl_xor_sync(0xffffffffu, cm1, 1));
            cm1 = fmaxf(cm1, __shfl_xor_sync(0xffffffffu, cm1, 2));
            float nm0 = fmaxf(m0, cm0), nm1 = fmaxf(m1, cm1);
            float f0 = __expf(m0 - nm0), f1 = __expf(m1 - nm1);
            m0 = nm0; m1 = nm1;
            den0 *= f0; den1 *= f1;
            #pragma unroll
            for (int nt = 0; nt < 2; nt++){
                oa[nt][0] *= f0; oa[nt][1] *= f0;
                oa[nt][2] *= f1; oa[nt][3] *= f1;
            }
            #pragma unroll
            for (int st = 0; st < 5; st++){
                float p0 = __expf(sc[st][0] - m0);
                float p1 = __expf(sc[st][1] - m0);
                float p2 = __expf(sc[st][2] - m1);
                float p3 = __expf(sc[st][3] - m1);
                den0 += p0 + p1; den1 += p2 + p3;
                *(float2*)(Pw + r*ATTN_P_P + st*8 + 2*cq)     = make_float2(to_tf32(p0), to_tf32(p1));
                *(float2*)(Pw + (r+8)*ATTN_P_P + st*8 + 2*cq) = make_float2(to_tf32(p2), to_tf32(p3));
            }
            __syncwarp();
            #pragma unroll
            for (int kf = 0; kf < 5; kf++){
                float4 a;
                a.x = Pw[r*ATTN_P_P + kf*8 + cq];
                a.y = Pw[(r+8)*ATTN_P_P + kf*8 + cq];
                a.z = Pw[r*ATTN_P_P + kf*8 + cq + 4];
                a.w = Pw[(r+8)*ATTN_P_P + kf*8 + cq + 4];
                const float* vb  = Vsm + (kc + kf*8 + cq    )*ATTN_V_P + r;
                const float* vb4 = Vsm + (kc + kf*8 + cq + 4)*ATTN_V_P + r;
                mma_tf32(oa[0], a, vb[0], vb4[0]);
                mma_tf32(oa[1], a, vb[8], vb4[8]);
            }
            __syncwarp();
        }
        den0 += __shfl_xor_sync(0xffffffffu, den0, 1);
        den0 += __shfl_xor_sync(0xffffffffu, den0, 2);
        den1 += __shfl_xor_sync(0xffffffffu, den1, 1);
        den1 += __shfl_xor_sync(0xffffffffu, den1, 2);
        float i0 = 1.f/den0, i1 = 1.f/den1;
        int row0 = mo + r, row1 = mo + r + 8;
        #pragma unroll
        for (int nt = 0; nt < 2; nt++){
            int d0 = nt*8 + 2*cq;
            g_scr[obase + (size_t)d0*Ln + row0]     = oa[nt][0]*i0;
            g_scr[obase + (size_t)(d0+1)*Ln + row0] = oa[nt][1]*i0;
            g_scr[obase + (size_t)d0*Ln + row1]     = oa[nt][2]*i1;
            g_scr[obase + (size_t)(d0+1)*Ln + row1] = oa[nt][3]*i1;
        }
    }
}

// ---------------- host launcher ----------------
extern "C" void kernel_launch(void* const* d_in, const int* in_sizes, int n_in,
                              void* d_out, int out_size){
    (void)in_sizes; (void)n_in; (void)out_size;
    const float* x    = (const float*)d_in[0];
    const float* mask = (const float*)d_in[1];
    const float* dw_w = (const float*)d_in[2];
    const float* dw_b = (const float*)d_in[3];
    const float* pw_w = (const float*)d_in[4];
    const float* pw_b = (const float*)d_in[5];
    const float* wq   = (const float*)d_in[6];
    const float* bq   = (const float*)d_in[7];
    const float* wk   = (const float*)d_in[8];
    const float* bk   = (const float*)d_in[9];
    const float* wv   = (const float*)d_in[10];
    const float* bv   = (const float*)d_in[11];
    const float* wo   = (const float*)d_in[12];
    const float* bo   = (const float*)d_in[13];
    const float* fc_w = (const float*)d_in[14];
    const float* fc_b = (const float*)d_in[15];
    const float* ln_g = (const float*)d_in[16];
    const float* ln_b = (const float*)d_in[17];
    float* outp = (float*)d_out;

    float *bufA, *bufB, *scr, *pA, *pB, *bqs;
    float4* wf;
    cudaGetSymbolAddress((void**)&bufA, g_bufA);
    cudaGetSymbolAddress((void**)&bufB, g_bufB);
    cudaGetSymbolAddress((void**)&scr,  g_scr);
    cudaGetSymbolAddress((void**)&pA,   g_partA);
    cudaGetSymbolAddress((void**)&pB,   g_partB);
    cudaGetSymbolAddress((void**)&wf,   g_wfrag);
    cudaGetSymbolAddress((void**)&bqs,  g_bqs);

    const int CONV_SMEM = CONV_SMEM_F * 4;
    const int MM_SMEM   = MM_SMEM_F * 4;
    const int QKV_SMEM  = QKV_SMEM_F * 4;
    const int ATTN_SMEM = ATTN_SMEM_F * 4;
    cudaFuncSetAttribute(k_attn, cudaFuncAttributeMaxDynamicSharedMemorySize, ATTN_SMEM);

    // stage 0: weight fragment packing + ln pack
    k_prep<<<(CLn + 255)/256, 256>>>(pw_w, wq, wk, wv, wo, fc_w, bq, ln_g, ln_b);

    // stage 1: x + pos, LN partials -> pA
    k_pos<<<dim3(Bn, 50), 256>>>(x);

    // stage 2: 4 fused conv layers
    float* cin  = bufA;
    float* cout = bufB;
    const float* pin = pA;
    float* pout = pB;
    int nparts = 50;
    for (int i = 0; i < 4; i++){
        k_conv<<<dim3(Bn, NLT64), 256, CONV_SMEM>>>(cin, cout,
            wf + i*4096, dw_w + i*Cn*Kn, dw_b + i*Cn, pw_b + i*Cn,
            pin, pout, nparts);
        float* t = cin; cin = cout; cout = t;
        float* tp = (float*)pin; pin = pout; pout = tp;
        nparts = NLT64;
    }
    // cin = residual after 4 conv layers; partials in pin (nparts=7)

    // stage 3: attention
    k_qkv<<<dim3(Bn, NLT32), 256, QKV_SMEM>>>(cin, bqs, bk, bv, pin, nparts);
    k_attn<<<Bn*Hn, 256, ATTN_SMEM>>>(mask);
    k_mm<false,false,true><<<dim3(Bn, NLT64), 256, MM_SMEM>>>(scr, cin, cout,
        wf + 7*4096, bo, nullptr, pout, 0);

    // stage 4: FC + relu + residual -> final output
    k_mm<true,true,false><<<dim3(Bn, NLT64), 256, MM_SMEM>>>(cout, cout, outp,
        wf + 8*4096, fc_b, pout, nullptr, NLT64);
}

// round 14
// speedup vs baseline: 1.0090x; 1.0090x over previous
#include <cuda_runtime.h>

#define Bn 64
#define Cn 128
#define Ln 400
#define Hn 8
#define Kn 7
#define CLn (Cn*Ln)            // 51200
#define BCL (Bn*Cn*Ln)         // 3276800
#define EPSf 1e-5f
#define LT64 64
#define NLT64 7
#define LT32 32
#define NLT32 13
#define QSCALE 0.08838834764831845f

// ---------------- scratch ----------------
__device__ float g_bufA[BCL];
__device__ float g_bufB[BCL];
__device__ float g_scr[BCL];     // attention output (B,C,L)
__device__ float g_q[BCL];       // (B,H,L,DK)
__device__ float g_k[BCL];
__device__ float g_v[BCL];
__device__ float g_partA[Bn*64*2];
__device__ float g_partB[Bn*64*2];
__device__ float4 g_wfrag[9*4096]; // mma A-fragments: [m][w(8)][k(16)][lane(32)]
__device__ float g_bqs[Cn];
__device__ float2 g_ln2[CLn];
__device__ float g_pose[CLn];    // positional encoding table (batch-invariant)

// ---------------- helpers ----------------
typedef unsigned long long u64;
__device__ __forceinline__ float to_tf32(float x){
    unsigned u; asm("cvt.rna.tf32.f32 %0, %1;" : "=r"(u) : "f"(x));
    return __uint_as_float(u);
}
__device__ __forceinline__ void mma_tf32(float* c, float4 a, float b0, float b1){
    asm volatile("mma.sync.aligned.m16n8k8.row.col.f32.tf32.tf32.f32 "
        "{%0,%1,%2,%3}, {%4,%5,%6,%7}, {%8,%9}, {%0,%1,%2,%3};"
        : "+f"(c[0]), "+f"(c[1]), "+f"(c[2]), "+f"(c[3])
        : "r"(__float_as_uint(a.x)), "r"(__float_as_uint(a.y)),
          "r"(__float_as_uint(a.z)), "r"(__float_as_uint(a.w)),
          "r"(__float_as_uint(b0)), "r"(__float_as_uint(b1)));
}

__device__ __forceinline__ void block_reduce2(float s, float ss, float* out2, float* red){
    #pragma unroll
    for (int o = 16; o > 0; o >>= 1){
        s  += __shfl_down_sync(0xffffffffu, s,  o);
        ss += __shfl_down_sync(0xffffffffu, ss, o);
    }
    int w = threadIdx.x >> 5;
    if ((threadIdx.x & 31) == 0){ red[w*2] = s; red[w*2+1] = ss; }
    __syncthreads();
    if (threadIdx.x == 0){
        float a = 0.f, b = 0.f;
        int nw = blockDim.x >> 5;
        for (int i = 0; i < nw; i++){ a += red[i*2]; b += red[i*2+1]; }
        out2[0] = a; out2[1] = b;
    }
}

__device__ __forceinline__ void stats_from_parts(const float* partIn, int b, int nparts, float* red){
    if (threadIdx.x < 32){
        float s = 0.f, ss = 0.f;
        for (int i = threadIdx.x; i < nparts; i += 32){
            s  += partIn[(b*64+i)*2];
            ss += partIn[(b*64+i)*2+1];
        }
        #pragma unroll
        for (int o = 16; o > 0; o >>= 1){
            s  += __shfl_down_sync(0xffffffffu, s,  o);
            ss += __shfl_down_sync(0xffffffffu, ss, o);
        }
        if (threadIdx.x == 0){
            float mu  = s / (float)CLn;
            float var = ss / (float)CLn - mu*mu;
            red[0] = mu;
            red[1] = rsqrtf(var + EPSf);
        }
    }
}

// ---------------- prep: weight frags + ln pack + pos table ----------------
__global__ __launch_bounds__(256) void k_prep(
        const float* __restrict__ pw, const float* __restrict__ wq,
        const float* __restrict__ wk, const float* __restrict__ wv,
        const float* __restrict__ wo, const float* __restrict__ fcw,
        const float* __restrict__ bq,
        const float* __restrict__ lng, const float* __restrict__ lnb){
    int idx = blockIdx.x*256 + threadIdx.x;
    if (idx < 9*4096){
        int m = idx >> 12;
        int rest = idx & 4095;
        int w = rest >> 9;
        int k = (rest >> 5) & 15;
        int lane = rest & 31;
        int r = lane >> 2, cq = lane & 3;
        const float* src = (m < 4) ? (pw + m*Cn*Cn) :
                           (m == 4) ? wq : (m == 5) ? wk : (m == 6) ? wv :
                           (m == 7) ? wo : fcw;
        float sc = (m == 4) ? QSCALE : 1.f;
        int mo = w*16, c0 = k*8;
        float a0 = to_tf32(src[(mo + r    )*Cn + c0 + cq    ] * sc);
        float a1 = to_tf32(src[(mo + r + 8)*Cn + c0 + cq    ] * sc);
        float a2 = to_tf32(src[(mo + r    )*Cn + c0 + cq + 4] * sc);
        float a3 = to_tf32(src[(mo + r + 8)*Cn + c0 + cq + 4] * sc);
        g_wfrag[idx] = make_float4(a0, a1, a2, a3);
    }
    if (idx < CLn){
        g_ln2[idx] = make_float2(lng[idx], lnb[idx]);
        // positional encoding table: batch-invariant
        int c = idx / Ln, l = idx - c*Ln;
        float fc, ph;
        if ((c & 1) == 0){ fc =  powf(10000.f, -(float)c/128.f);       ph = 0.f; }
        else             { fc = -powf(10000.f, (1.f-(float)c)/128.f);  ph = 1.5707963267948966f; }
        g_pose[idx] = sinf((float)l*fc + ph);
    }
    if (idx < Cn) g_bqs[idx] = bq[idx] * QSCALE;
}

// ---------------- x + positional encoding (table add), + LN partials ----------------
__global__ __launch_bounds__(256) void k_pos(const float* __restrict__ x){
    __shared__ float red[16];
    int tid = threadIdx.x;
    int b  = blockIdx.x;
    int i4 = blockIdx.y * 256 + tid;
    float4 xv = ((const float4*)x)[b*(CLn/4) + i4];
    float4 pv = ((const float4*)g_pose)[i4];
    float v0 = xv.x + pv.x;
    float v1 = xv.y + pv.y;
    float v2 = xv.z + pv.z;
    float v3 = xv.w + pv.w;
    ((float4*)g_bufA)[b*(CLn/4) + i4] = make_float4(v0, v1, v2, v3);
    float s  = v0 + v1 + v2 + v3;
    float ss = v0*v0 + v1*v1 + v2*v2 + v3*v3;
    block_reduce2(s, ss, &g_partA[(b*64 + blockIdx.y)*2], red);
}

// ===== GEMM mainloop, 8 n-tiles (64 cols), pitch P (P mod 32 == 8 -> conflict-free) =====
#define GEMM_MMA8(WFp, XS, P)                                                   \
    int lane = tid & 31, w = tid >> 5;                                          \
    int r = lane >> 2, cq = lane & 3;                                           \
    float acc[8][4];                                                            \
    _Pragma("unroll")                                                           \
    for (int nt = 0; nt < 8; nt++){                                             \
        acc[nt][0] = 0.f; acc[nt][1] = 0.f; acc[nt][2] = 0.f; acc[nt][3] = 0.f; \
    }                                                                           \
    {                                                                           \
        const float4* af = (WFp) + w*512 + lane;                                \
        _Pragma("unroll")                                                       \
        for (int k = 0; k < 16; k++){                                           \
            float4 a = af[k*32];                                                \
            const float* xb = (XS) + (k*8 + cq)*(P) + r;                        \
            _Pragma("unroll")                                                   \
            for (int nt = 0; nt < 8; nt++){                                     \
                mma_tf32(acc[nt], a, xb[nt*8], xb[4*(P) + nt*8]);               \
            }                                                                   \
        }                                                                       \
    }

// ---------------- fused conv layer ----------------
// grid (B, NLT64), block 256
// smem: XsmH [c][70] pitch 72 (x halo; depthwise writes y[c][l] to index l+6 in-place)
#define CONV_SMEM_F (9216 + 1024 + 128 + 16)
__global__ __launch_bounds__(256, 4) void k_conv(
        const float* __restrict__ in, float* __restrict__ out,
        const float4* __restrict__ Wf,
        const float* __restrict__ dw, const float* __restrict__ db,
        const float* __restrict__ pb,
        const float* __restrict__ partIn, float* __restrict__ partOut, int nparts){
    extern __shared__ float sm[];
    float* XsmH = sm;                  // [c][70] pitch 72 ; y aliased at +6
    float* Dw   = sm + 9216;
    float* Db   = Dw + 1024;
    float* red  = Db + 128;
    int b = blockIdx.x, lt = blockIdx.y, tid = threadIdx.x;
    int l0 = lt * LT64;

    stats_from_parts(partIn, b, nparts, red);
    for (int idx = tid; idx < Cn*Kn; idx += 256)
        Dw[(idx/7)*8 + (idx - (idx/7)*7)] = dw[idx];
    if (tid < Cn) Db[tid] = db[tid];
    __syncthreads();
    float mu = red[0], rs = red[1];
    for (int idx = tid; idx < Cn*70; idx += 256){
        int c = idx / 70, j = idx - c*70;
        int gl = l0 - 3 + j;
        float v = 0.f;
        if (gl >= 0 && gl < Ln){
            float2 gb = g_ln2[c*Ln + gl];
            float a = rs*gb.x;
            v = fmaf(in[(b*Cn + c)*Ln + gl], a, fmaf(-mu, a, gb.y));
        }
        XsmH[c*72 + j] = v;
    }
    __syncthreads();
    // depthwise in-place: y[c][l] -> index l+6 (the x cell read in the same iteration)
    {
        int c  = tid >> 1;
        int lb = (tid & 1) * 32;
        float* xr = XsmH + c*72 + lb;
        float d0 = Dw[c*8+0], d1 = Dw[c*8+1], d2 = Dw[c*8+2], d3 = Dw[c*8+3];
        float d4 = Dw[c*8+4], d5 = Dw[c*8+5], d6 = Dw[c*8+6];
        float bias = Db[c];
        float w0 = xr[0], w1 = xr[1], w2 = xr[2], w3 = xr[3], w4 = xr[4], w5 = xr[5];
        __syncwarp();   // all preloads (x[lb..lb+5]) before any in-place writes
        #pragma unroll
        for (int l = 0; l < 32; l++){
            float w6 = xr[l + 6];
            float a = bias;
            a = fmaf(w0, d0, a); a = fmaf(w1, d1, a); a = fmaf(w2, d2, a);
            a = fmaf(w3, d3, a); a = fmaf(w4, d4, a); a = fmaf(w5, d5, a);
            a = fmaf(w6, d6, a);
            xr[l + 6] = to_tf32(a);          // overwrite the cell just read
            w0 = w1; w1 = w2; w2 = w3; w3 = w4; w4 = w5; w5 = w6;
        }
    }
    __syncthreads();

    GEMM_MMA8(Wf, XsmH + 6, 72)

    int mo = w*16;
    float s = 0.f, ss = 0.f;
    #pragma unroll
    for (int nt = 0; nt < 8; nt++){
        int col = l0 + nt*8 + 2*cq;
        if (col < Ln){
            int o1 = mo + r, o2 = o1 + 8;
            float b1v = pb[o1], b2v = pb[o2];
            float z0 = acc[nt][0] + b1v, z1 = acc[nt][1] + b1v;
            float z2 = acc[nt][2] + b2v, z3 = acc[nt][3] + b2v;
            z0 = z0 > 0.f ? z0 : 0.f;  z1 = z1 > 0.f ? z1 : 0.f;
            z2 = z2 > 0.f ? z2 : 0.f;  z3 = z3 > 0.f ? z3 : 0.f;
            float2 r1 = *(const float2*)&in[(b*Cn + o1)*Ln + col];
            float2 r2 = *(const float2*)&in[(b*Cn + o2)*Ln + col];
            float v0 = r1.x + z0, v1 = r1.y + z1;
            float v2 = r2.x + z2, v3 = r2.y + z3;
            *(float2*)&out[(b*Cn + o1)*Ln + col] = make_float2(v0, v1);
            *(float2*)&out[(b*Cn + o2)*Ln + col] = make_float2(v2, v3);
            s  += v0 + v1 + v2 + v3;
            ss += v0*v0 + v1*v1 + v2*v2 + v3*v3;
        }
    }
    block_reduce2(s, ss, &partOut[(b*64 + lt)*2], red);
}

// ---------------- generic matmul ----------------
// grid (B, NLT64), block 256
#define MM_SMEM_F (9216 + 16)
template<bool LN, bool RELU, bool STATS>
__global__ __launch_bounds__(256, 4) void k_mm(
        const float* __restrict__ in, const float* resid, float* __restrict__ out,
        const float4* __restrict__ Wf, const float* __restrict__ bias,
        const float* __restrict__ partIn, float* __restrict__ partOut, int nparts){
    extern __shared__ float sm[];
    float* Xsm = sm;                 // [c][64] pitch 72
    float* red = sm + 9216;
    int b = blockIdx.x, lt = blockIdx.y, tid = threadIdx.x;
    int l0 = lt * LT64;
    if (LN) stats_from_parts(partIn, b, nparts, red);
    __syncthreads();
    float mu = 0.f, rs = 1.f;
    if (LN){ mu = red[0]; rs = red[1]; }
    for (int idx = tid; idx < Cn*LT64; idx += 256){
        int c = idx >> 6, j = idx & 63;
        int gl = l0 + j;
        float v = 0.f;
        if (gl < Ln){
            v = in[(b*Cn + c)*Ln + gl];
            if (LN){
                float2 gb = g_ln2[c*Ln + gl];
                float a = rs*gb.x;
                v = fmaf(v, a, fmaf(-mu, a, gb.y));
            }
        }
        Xsm[c*72 + j] = to_tf32(v);
    }
    __syncthreads();

    GEMM_MMA8(Wf, Xsm, 72)

    int mo = w*16;
    float s = 0.f, ss = 0.f;
    #pragma unroll
    for (int nt = 0; nt < 8; nt++){
        int col = l0 + nt*8 + 2*cq;
        if (col < Ln){
            int o1 = mo + r, o2 = o1 + 8;
            float b1v = bias[o1], b2v = bias[o2];
            float z0 = acc[nt][0] + b1v, z1 = acc[nt][1] + b1v;
            float z2 = acc[nt][2] + b2v, z3 = acc[nt][3] + b2v;
            if (RELU){
                z0 = z0 > 0.f ? z0 : 0.f;  z1 = z1 > 0.f ? z1 : 0.f;
                z2 = z2 > 0.f ? z2 : 0.f;  z3 = z3 > 0.f ? z3 : 0.f;
            }
            float2 r1 = *(const float2*)&resid[(b*Cn + o1)*Ln + col];
            float2 r2 = *(const float2*)&resid[(b*Cn + o2)*Ln + col];
            float v0 = r1.x + z0, v1 = r1.y + z1;
            float v2 = r2.x + z2, v3 = r2.y + z3;
            *(float2*)&out[(b*Cn + o1)*Ln + col] = make_float2(v0, v1);
            *(float2*)&out[(b*Cn + o2)*Ln + col] = make_float2(v2, v3);
            if (STATS){
                s  += v0 + v1 + v2 + v3;
                ss += v0*v0 + v1*v1 + v2*v2 + v3*v3;
            }
        }
    }
    if (STATS) block_reduce2(s, ss, &partOut[(b*64 + lt)*2], red);
}

// ---------------- merged QKV (stage X once, 3 A-streams) ----------------
// grid (B, NLT32), block 256 ; X [c][32] pitch 40
#define QKV_SMEM_F (5120 + 16)
__global__ __launch_bounds__(256, 3) void k_qkv(
        const float* __restrict__ in,
        const float* __restrict__ bq_s, const float* __restrict__ bk,
        const float* __restrict__ bv,
        const float* __restrict__ partIn, int nparts){
    extern __shared__ float sm[];
    float* Xsm = sm;
    float* red = sm + 5120;
    int b = blockIdx.x, lt = blockIdx.y, tid = threadIdx.x;
    int l0 = lt * LT32;
    stats_from_parts(partIn, b, nparts, red);
    __syncthreads();
    float mu = red[0], rs = red[1];
    for (int idx = tid; idx < Cn*LT32; idx += 256){
        int c = idx >> 5, j = idx & 31;
        int gl = l0 + j;
        float v = 0.f;
        if (gl < Ln){
            float2 gb = g_ln2[c*Ln + gl];
            float a = rs*gb.x;
            v = fmaf(in[(b*Cn + c)*Ln + gl], a, fmaf(-mu, a, gb.y));
        }
        Xsm[c*40 + j] = to_tf32(v);
    }
    __syncthreads();

    int lane = tid & 31, w = tid >> 5;
    int r = lane >> 2, cq = lane & 3;
    float acc[3][4][4];
    #pragma unroll
    for (int m = 0; m < 3; m++)
        #pragma unroll
        for (int nt = 0; nt < 4; nt++){
            acc[m][nt][0] = 0.f; acc[m][nt][1] = 0.f;
            acc[m][nt][2] = 0.f; acc[m][nt][3] = 0.f;
        }
    {
        const float4* af0 = g_wfrag + 4*4096 + w*512 + lane;
        const float4* af1 = af0 + 4096;
        const float4* af2 = af1 + 4096;
        #pragma unroll
        for (int k = 0; k < 16; k++){
            float4 aq = af0[k*32];
            float4 ak = af1[k*32];
            float4 av = af2[k*32];
            const float* xb = Xsm + (k*8 + cq)*40 + r;
            #pragma unroll
            for (int nt = 0; nt < 4; nt++){
                float b0 = xb[nt*8];
                float b1 = xb[4*40 + nt*8];
                mma_tf32(acc[0][nt], aq, b0, b1);
                mma_tf32(acc[1][nt], ak, b0, b1);
                mma_tf32(acc[2][nt], av, b0, b1);
            }
        }
    }

    int o1 = w*16 + r, o2 = o1 + 8;
    #pragma unroll
    for (int m = 0; m < 3; m++){
        const float* bias = (m == 0) ? bq_s : (m == 1) ? bk : bv;
        float* outp       = (m == 0) ? g_q  : (m == 1) ? g_k : g_v;
        float b1v = bias[o1], b2v = bias[o2];
        #pragma unroll
        for (int nt = 0; nt < 4; nt++){
            int col = l0 + nt*8 + 2*cq;
            if (col < Ln){
                float* p = outp + ((size_t)(b*Hn + w)*Ln + col)*16;
                p[r]          = acc[m][nt][0] + b1v;
                p[16 + r]     = acc[m][nt][1] + b1v;
                p[r + 8]      = acc[m][nt][2] + b2v;
                p[16 + r + 8] = acc[m][nt][3] + b2v;
            }
        }
    }
}

// ---------------- attention: flash-style tf32 mma ----------------
#define ATTN_K_P 20
#define ATTN_V_P 24
#define ATTN_P_P 44
#define ATTN_SMEM_F (Ln*ATTN_K_P + Ln*ATTN_V_P + Ln + 8*16*ATTN_P_P)
__global__ __launch_bounds__(256, 2) void k_attn(const float* __restrict__ mask){
    extern __shared__ float sm[];
    float* Ksm = sm;                                  // pitch 20
    float* Vsm = sm + Ln*ATTN_K_P;                    // pitch 24
    float* Msm = Vsm + Ln*ATTN_V_P;
    float* Pall = Msm + Ln;
    int bh = blockIdx.x;
    int b = bh >> 3, h = bh & 7;
    int tid = threadIdx.x;
    {
        const float4* kp = (const float4*)(g_k + (size_t)bh*Ln*16);
        const float4* vp = (const float4*)(g_v + (size_t)bh*Ln*16);
        for (int i = tid; i < Ln*4; i += 256){
            int row = i >> 2, q = i & 3;
            float4 kv = kp[i];
            kv.x = to_tf32(kv.x); kv.y = to_tf32(kv.y);
            kv.z = to_tf32(kv.z); kv.w = to_tf32(kv.w);
            *(float4*)(Ksm + row*ATTN_K_P + q*4) = kv;
            float4 vv = vp[i];
            vv.x = to_tf32(vv.x); vv.y = to_tf32(vv.y);
            vv.z = to_tf32(vv.z); vv.w = to_tf32(vv.w);
            *(float4*)(Vsm + row*ATTN_V_P + q*4) = vv;
        }
        for (int i = tid; i < Ln; i += 256) Msm[i] = mask[b*Ln + i];
    }
    __syncthreads();

    int lane = tid & 31, w = tid >> 5;
    int r = lane >> 2, cq = lane & 3;
    float* Pw = Pall + w*16*ATTN_P_P;
    const float* Qbase = g_q + (size_t)bh*Ln*16;
    size_t obase = ((size_t)b*Cn + h*16)*Ln;

    for (int mt = w; mt < 25; mt += 8){
        int mo = mt*16;
        float4 qf0, qf1;
        qf0.x = to_tf32(Qbase[(mo + r    )*16 + cq    ]);
        qf0.y = to_tf32(Qbase[(mo + r + 8)*16 + cq    ]);
        qf0.z = to_tf32(Qbase[(mo + r    )*16 + cq + 4]);
        qf0.w = to_tf32(Qbase[(mo + r + 8)*16 + cq + 4]);
        qf1.x = to_tf32(Qbase[(mo + r    )*16 + 8 + cq    ]);
        qf1.y = to_tf32(Qbase[(mo + r + 8)*16 + 8 + cq    ]);
        qf1.z = to_tf32(Qbase[(mo + r    )*16 + 8 + cq + 4]);
        qf1.w = to_tf32(Qbase[(mo + r + 8)*16 + 8 + cq + 4]);

        float m0 = -3.0e38f, m1 = -3.0e38f, den0 = 0.f, den1 = 0.f;
        float oa[2][4];
        oa[0][0]=oa[0][1]=oa[0][2]=oa[0][3]=0.f;
        oa[1][0]=oa[1][1]=oa[1][2]=oa[1][3]=0.f;

        for (int kc = 0; kc < Ln; kc += 40){
            float sc[5][4];
            #pragma unroll
            for (int st = 0; st < 5; st++){
                sc[st][0]=0.f; sc[st][1]=0.f; sc[st][2]=0.f; sc[st][3]=0.f;
                const float* kb = Ksm + (kc + st*8 + r)*ATTN_K_P + cq;
                mma_tf32(sc[st], qf0, kb[0], kb[4]);
                mma_tf32(sc[st], qf1, kb[8], kb[12]);
            }
            #pragma unroll
            for (int st = 0; st < 5; st++){
                float2 mk = *(const float2*)(Msm + kc + st*8 + 2*cq);
                float a0 = (1.f - mk.x)*(-1e30f), a1 = (1.f - mk.y)*(-1e30f);
                sc[st][0] = sc[st][0]*mk.x + a0;
                sc[st][1] = sc[st][1]*mk.y + a1;
                sc[st][2] = sc[st][2]*mk.x + a0;
                sc[st][3] = sc[st][3]*mk.y + a1;
            }
            float cm0 = -3.0e38f, cm1 = -3.0e38f;
            #pragma unroll
            for (int st = 0; st < 5; st++){
                cm0 = fmaxf(cm0, fmaxf(sc[st][0], sc[st][1]));
                cm1 = fmaxf(cm1, fmaxf(sc[st][2], sc[st][3]));
            }
            cm0 = fmaxf(cm0, __shfl_xor_sync(0xffffffffu, cm0, 1));
            cm0 = fmaxf(cm0, __shfl_xor_sync(0xffffffffu, cm0, 2));
            cm1 = fmaxf(cm1, __shfl_xor_sync(0xffffffffu, cm1, 1));
            cm1 = fmaxf(cm1, __shfl_xor_sync(0xffffffffu, cm1, 2));
            float nm0 = fmaxf(m0, cm0), nm1 = fmaxf(m1, cm1);
            float f0 = __expf(m0 - nm0), f1 = __expf(m1 - nm1);
            m0 = nm0; m1 = nm1;
            den0 *= f0; den1 *= f1;
            #pragma unroll
            for (int nt = 0; nt < 2; nt++){
                oa[nt][0] *= f0; oa[nt][1] *= f0;
                oa[nt][2] *= f1; oa[nt][3] *= f1;
            }
            #pragma unroll
            for (int st = 0; st < 5; st++){
                float p0 = __expf(sc[st][0] - m0);
                float p1 = __expf(sc[st][1] - m0);
                float p2 = __expf(sc[st][2] - m1);
                float p3 = __expf(sc[st][3] - m1);
                den0 += p0 + p1; den1 += p2 + p3;
                *(float2*)(Pw + r*ATTN_P_P + st*8 + 2*cq)     = make_float2(to_tf32(p0), to_tf32(p1));
                *(float2*)(Pw + (r+8)*ATTN_P_P + st*8 + 2*cq) = make_float2(to_tf32(p2), to_tf32(p3));
            }
            __syncwarp();
            #pragma unroll
            for (int kf = 0; kf < 5; kf++){
                float4 a;
                a.x = Pw[r*ATTN_P_P + kf*8 + cq];
                a.y = Pw[(r+8)*ATTN_P_P + kf*8 + cq];
                a.z = Pw[r*ATTN_P_P + kf*8 + cq + 4];
                a.w = Pw[(r+8)*ATTN_P_P + kf*8 + cq + 4];
                const float* vb  = Vsm + (kc + kf*8 + cq    )*ATTN_V_P + r;
                const float* vb4 = Vsm + (kc + kf*8 + cq + 4)*ATTN_V_P + r;
                mma_tf32(oa[0], a, vb[0], vb4[0]);
                mma_tf32(oa[1], a, vb[8], vb4[8]);
            }
            __syncwarp();
        }
        den0 += __shfl_xor_sync(0xffffffffu, den0, 1);
        den0 += __shfl_xor_sync(0xffffffffu, den0, 2);
        den1 += __shfl_xor_sync(0xffffffffu, den1, 1);
        den1 += __shfl_xor_sync(0xffffffffu, den1, 2);
        float i0 = 1.f/den0, i1 = 1.f/den1;
        int row0 = mo + r, row1 = mo + r + 8;
        #pragma unroll
        for (int nt = 0; nt < 2; nt++){
            int d0 = nt*8 + 2*cq;
            g_scr[obase + (size_t)d0*Ln + row0]     = oa[nt][0]*i0;
            g_scr[obase + (size_t)(d0+1)*Ln + row0] = oa[nt][1]*i0;
            g_scr[obase + (size_t)d0*Ln + row1]     = oa[nt][2]*i1;
            g_scr[obase + (size_t)(d0+1)*Ln + row1] = oa[nt][3]*i1;
        }
    }
}

// ---------------- host launcher ----------------
extern "C" void kernel_launch(void* const* d_in, const int* in_sizes, int n_in,
                              void* d_out, int out_size){
    (void)in_sizes; (void)n_in; (void)out_size;
    const float* x    = (const float*)d_in[0];
    const float* mask = (const float*)d_in[1];
    const float* dw_w = (const float*)d_in[2];
    const float* dw_b = (const float*)d_in[3];
    const float* pw_w = (const float*)d_in[4];
    const float* pw_b = (const float*)d_in[5];
    const float* wq   = (const float*)d_in[6];
    const float* bq   = (const float*)d_in[7];
    const float* wk   = (const float*)d_in[8];
    const float* bk   = (const float*)d_in[9];
    const float* wv   = (const float*)d_in[10];
    const float* bv   = (const float*)d_in[11];
    const float* wo   = (const float*)d_in[12];
    const float* bo   = (const float*)d_in[13];
    const float* fc_w = (const float*)d_in[14];
    const float* fc_b = (const float*)d_in[15];
    const float* ln_g = (const float*)d_in[16];
    const float* ln_b = (const float*)d_in[17];
    float* outp = (float*)d_out;

    float *bufA, *bufB, *scr, *pA, *pB, *bqs;
    float4* wf;
    cudaGetSymbolAddress((void**)&bufA, g_bufA);
    cudaGetSymbolAddress((void**)&bufB, g_bufB);
    cudaGetSymbolAddress((void**)&scr,  g_scr);
    cudaGetSymbolAddress((void**)&pA,   g_partA);
    cudaGetSymbolAddress((void**)&pB,   g_partB);
    cudaGetSymbolAddress((void**)&wf,   g_wfrag);
    cudaGetSymbolAddress((void**)&bqs,  g_bqs);

    const int CONV_SMEM = CONV_SMEM_F * 4;
    const int MM_SMEM   = MM_SMEM_F * 4;
    const int QKV_SMEM  = QKV_SMEM_F * 4;
    const int ATTN_SMEM = ATTN_SMEM_F * 4;
    cudaFuncSetAttribute(k_attn, cudaFuncAttributeMaxDynamicSharedMemorySize, ATTN_SMEM);

    // stage 0: weight fragment packing + ln pack + pos table
    k_prep<<<(CLn + 255)/256, 256>>>(pw_w, wq, wk, wv, wo, fc_w, bq, ln_g, ln_b);

    // stage 1: x + pos (table add), LN partials -> pA
    k_pos<<<dim3(Bn, 50), 256>>>(x);

    // stage 2: 4 fused conv layers
    float* cin  = bufA;
    float* cout = bufB;
    const float* pin = pA;
    float* pout = pB;
    int nparts = 50;
    for (int i = 0; i < 4; i++){
        k_conv<<<dim3(Bn, NLT64), 256, CONV_SMEM>>>(cin, cout,
            wf + i*4096, dw_w + i*Cn*Kn, dw_b + i*Cn, pw_b + i*Cn,
            pin, pout, nparts);
        float* t = cin; cin = cout; cout = t;
        float* tp = (float*)pin; pin = pout; pout = tp;
        nparts = NLT64;
    }
    // cin = residual after 4 conv layers; partials in pin (nparts=7)

    // stage 3: attention
    k_qkv<<<dim3(Bn, NLT32), 256, QKV_SMEM>>>(cin, bqs, bk, bv, pin, nparts);
    k_attn<<<Bn*Hn, 256, ATTN_SMEM>>>(mask);
    k_mm<false,false,true><<<dim3(Bn, NLT64), 256, MM_SMEM>>>(scr, cin, cout,
        wf + 7*4096, bo, nullptr, pout, 0);

    // stage 4: FC + relu + residual -> final output
    k_mm<true,true,false><<<dim3(Bn, NLT64), 256, MM_SMEM>>>(cout, cout, outp,
        wf + 8*4096, fc_b, pout, nullptr, NLT64);
}

// round 15
// speedup vs baseline: 1.0094x; 1.0004x over previous
#include <cuda_runtime.h>

#define Bn 64
#define Cn 128
#define Ln 400
#define Hn 8
#define Kn 7
#define CLn (Cn*Ln)            // 51200
#define BCL (Bn*Cn*Ln)         // 3276800
#define EPSf 1e-5f
#define LT64 64
#define NLT64 7
#define QSCALE 0.08838834764831845f

// ---------------- scratch ----------------
__device__ float g_bufA[BCL];
__device__ float g_bufB[BCL];
__device__ float g_scr[BCL];     // attention output (B,C,L)
__device__ float g_q[BCL];       // (B,H,L,DK)
__device__ float g_k[BCL];
__device__ float g_v[BCL];
__device__ float g_partA[Bn*64*2];
__device__ float g_partB[Bn*64*2];
__device__ float4 g_wfrag[9*4096]; // mma A-fragments: [m][w(8)][k(16)][lane(32)]
__device__ float g_bqs[Cn];
__device__ float2 g_ln2[CLn];
__device__ float g_pose[CLn];    // positional encoding table (batch-invariant)

// ---------------- helpers ----------------
typedef unsigned long long u64;
__device__ __forceinline__ float to_tf32(float x){
    unsigned u; asm("cvt.rna.tf32.f32 %0, %1;" : "=r"(u) : "f"(x));
    return __uint_as_float(u);
}
__device__ __forceinline__ void mma_tf32(float* c, float4 a, float b0, float b1){
    asm volatile("mma.sync.aligned.m16n8k8.row.col.f32.tf32.tf32.f32 "
        "{%0,%1,%2,%3}, {%4,%5,%6,%7}, {%8,%9}, {%0,%1,%2,%3};"
        : "+f"(c[0]), "+f"(c[1]), "+f"(c[2]), "+f"(c[3])
        : "r"(__float_as_uint(a.x)), "r"(__float_as_uint(a.y)),
          "r"(__float_as_uint(a.z)), "r"(__float_as_uint(a.w)),
          "r"(__float_as_uint(b0)), "r"(__float_as_uint(b1)));
}

__device__ __forceinline__ void block_reduce2(float s, float ss, float* out2, float* red){
    #pragma unroll
    for (int o = 16; o > 0; o >>= 1){
        s  += __shfl_down_sync(0xffffffffu, s,  o);
        ss += __shfl_down_sync(0xffffffffu, ss, o);
    }
    int w = threadIdx.x >> 5;
    if ((threadIdx.x & 31) == 0){ red[w*2] = s; red[w*2+1] = ss; }
    __syncthreads();
    if (threadIdx.x == 0){
        float a = 0.f, b = 0.f;
        int nw = blockDim.x >> 5;
        for (int i = 0; i < nw; i++){ a += red[i*2]; b += red[i*2+1]; }
        out2[0] = a; out2[1] = b;
    }
}

__device__ __forceinline__ void stats_from_parts(const float* partIn, int b, int nparts, float* red){
    if (threadIdx.x < 32){
        float s = 0.f, ss = 0.f;
        for (int i = threadIdx.x; i < nparts; i += 32){
            s  += partIn[(b*64+i)*2];
            ss += partIn[(b*64+i)*2+1];
        }
        #pragma unroll
        for (int o = 16; o > 0; o >>= 1){
            s  += __shfl_down_sync(0xffffffffu, s,  o);
            ss += __shfl_down_sync(0xffffffffu, ss, o);
        }
        if (threadIdx.x == 0){
            float mu  = s / (float)CLn;
            float var = ss / (float)CLn - mu*mu;
            red[0] = mu;
            red[1] = rsqrtf(var + EPSf);
        }
    }
}

// ---------------- prep: weight frags + ln pack + pos table ----------------
__global__ __launch_bounds__(256) void k_prep(
        const float* __restrict__ pw, const float* __restrict__ wq,
        const float* __restrict__ wk, const float* __restrict__ wv,
        const float* __restrict__ wo, const float* __restrict__ fcw,
        const float* __restrict__ bq,
        const float* __restrict__ lng, const float* __restrict__ lnb){
    int idx = blockIdx.x*256 + threadIdx.x;
    if (idx < 9*4096){
        int m = idx >> 12;
        int rest = idx & 4095;
        int w = rest >> 9;
        int k = (rest >> 5) & 15;
        int lane = rest & 31;
        int r = lane >> 2, cq = lane & 3;
        const float* src = (m < 4) ? (pw + m*Cn*Cn) :
                           (m == 4) ? wq : (m == 5) ? wk : (m == 6) ? wv :
                           (m == 7) ? wo : fcw;
        float sc = (m == 4) ? QSCALE : 1.f;
        int mo = w*16, c0 = k*8;
        float a0 = to_tf32(src[(mo + r    )*Cn + c0 + cq    ] * sc);
        float a1 = to_tf32(src[(mo + r + 8)*Cn + c0 + cq    ] * sc);
        float a2 = to_tf32(src[(mo + r    )*Cn + c0 + cq + 4] * sc);
        float a3 = to_tf32(src[(mo + r + 8)*Cn + c0 + cq + 4] * sc);
        g_wfrag[idx] = make_float4(a0, a1, a2, a3);
    }
    if (idx < CLn){
        g_ln2[idx] = make_float2(lng[idx], lnb[idx]);
        int c = idx / Ln, l = idx - c*Ln;
        float fc, ph;
        if ((c & 1) == 0){ fc =  powf(10000.f, -(float)c/128.f);       ph = 0.f; }
        else             { fc = -powf(10000.f, (1.f-(float)c)/128.f);  ph = 1.5707963267948966f; }
        g_pose[idx] = sinf((float)l*fc + ph);
    }
    if (idx < Cn) g_bqs[idx] = bq[idx] * QSCALE;
}

// ---------------- x + positional encoding (table add), + LN partials ----------------
__global__ __launch_bounds__(256) void k_pos(const float* __restrict__ x){
    __shared__ float red[16];
    int tid = threadIdx.x;
    int b  = blockIdx.x;
    int i4 = blockIdx.y * 256 + tid;
    float4 xv = ((const float4*)x)[b*(CLn/4) + i4];
    float4 pv = ((const float4*)g_pose)[i4];
    float v0 = xv.x + pv.x;
    float v1 = xv.y + pv.y;
    float v2 = xv.z + pv.z;
    float v3 = xv.w + pv.w;
    ((float4*)g_bufA)[b*(CLn/4) + i4] = make_float4(v0, v1, v2, v3);
    float s  = v0 + v1 + v2 + v3;
    float ss = v0*v0 + v1*v1 + v2*v2 + v3*v3;
    block_reduce2(s, ss, &g_partA[(b*64 + blockIdx.y)*2], red);
}

// ===== GEMM mainloop, 8 n-tiles (64 cols), pitch P (P mod 32 == 8 -> conflict-free) =====
#define GEMM_MMA8(WFp, XS, P)                                                   \
    int lane = tid & 31, w = tid >> 5;                                          \
    int r = lane >> 2, cq = lane & 3;                                           \
    float acc[8][4];                                                            \
    _Pragma("unroll")                                                           \
    for (int nt = 0; nt < 8; nt++){                                             \
        acc[nt][0] = 0.f; acc[nt][1] = 0.f; acc[nt][2] = 0.f; acc[nt][3] = 0.f; \
    }                                                                           \
    {                                                                           \
        const float4* af = (WFp) + w*512 + lane;                                \
        _Pragma("unroll")                                                       \
        for (int k = 0; k < 16; k++){                                           \
            float4 a = af[k*32];                                                \
            const float* xb = (XS) + (k*8 + cq)*(P) + r;                        \
            _Pragma("unroll")                                                   \
            for (int nt = 0; nt < 8; nt++){                                     \
                mma_tf32(acc[nt], a, xb[nt*8], xb[4*(P) + nt*8]);               \
            }                                                                   \
        }                                                                       \
    }

// ---------------- fused conv layer ----------------
// grid (B, NLT64), block 256
// smem: XsmH [c][70] pitch 72 (x halo; depthwise writes y[c][l] to index l+6 in-place)
#define CONV_SMEM_F (9216 + 1024 + 128 + 16)
__global__ __launch_bounds__(256, 4) void k_conv(
        const float* __restrict__ in, float* __restrict__ out,
        const float4* __restrict__ Wf,
        const float* __restrict__ dw, const float* __restrict__ db,
        const float* __restrict__ pb,
        const float* __restrict__ partIn, float* __restrict__ partOut, int nparts){
    extern __shared__ float sm[];
    float* XsmH = sm;                  // [c][70] pitch 72 ; y aliased at +6
    float* Dw   = sm + 9216;
    float* Db   = Dw + 1024;
    float* red  = Db + 128;
    int b = blockIdx.x, lt = blockIdx.y, tid = threadIdx.x;
    int l0 = lt * LT64;

    stats_from_parts(partIn, b, nparts, red);
    for (int idx = tid; idx < Cn*Kn; idx += 256)
        Dw[(idx/7)*8 + (idx - (idx/7)*7)] = dw[idx];
    if (tid < Cn) Db[tid] = db[tid];
    __syncthreads();
    float mu = red[0], rs = red[1];
    for (int idx = tid; idx < Cn*70; idx += 256){
        int c = idx / 70, j = idx - c*70;
        int gl = l0 - 3 + j;
        float v = 0.f;
        if (gl >= 0 && gl < Ln){
            float2 gb = g_ln2[c*Ln + gl];
            float a = rs*gb.x;
            v = fmaf(in[(b*Cn + c)*Ln + gl], a, fmaf(-mu, a, gb.y));
        }
        XsmH[c*72 + j] = v;
    }
    __syncthreads();
    // depthwise in-place: y[c][l] -> index l+6 (the x cell read in the same iteration)
    {
        int c  = tid >> 1;
        int lb = (tid & 1) * 32;
        float* xr = XsmH + c*72 + lb;
        float d0 = Dw[c*8+0], d1 = Dw[c*8+1], d2 = Dw[c*8+2], d3 = Dw[c*8+3];
        float d4 = Dw[c*8+4], d5 = Dw[c*8+5], d6 = Dw[c*8+6];
        float bias = Db[c];
        float w0 = xr[0], w1 = xr[1], w2 = xr[2], w3 = xr[3], w4 = xr[4], w5 = xr[5];
        __syncwarp();   // all preloads (x[lb..lb+5]) before any in-place writes
        #pragma unroll
        for (int l = 0; l < 32; l++){
            float w6 = xr[l + 6];
            float a = bias;
            a = fmaf(w0, d0, a); a = fmaf(w1, d1, a); a = fmaf(w2, d2, a);
            a = fmaf(w3, d3, a); a = fmaf(w4, d4, a); a = fmaf(w5, d5, a);
            a = fmaf(w6, d6, a);
            xr[l + 6] = to_tf32(a);          // overwrite the cell just read
            w0 = w1; w1 = w2; w2 = w3; w3 = w4; w4 = w5; w5 = w6;
        }
    }
    __syncthreads();

    GEMM_MMA8(Wf, XsmH + 6, 72)

    int mo = w*16;
    float s = 0.f, ss = 0.f;
    #pragma unroll
    for (int nt = 0; nt < 8; nt++){
        int col = l0 + nt*8 + 2*cq;
        if (col < Ln){
            int o1 = mo + r, o2 = o1 + 8;
            float b1v = pb[o1], b2v = pb[o2];
            float z0 = acc[nt][0] + b1v, z1 = acc[nt][1] + b1v;
            float z2 = acc[nt][2] + b2v, z3 = acc[nt][3] + b2v;
            z0 = z0 > 0.f ? z0 : 0.f;  z1 = z1 > 0.f ? z1 : 0.f;
            z2 = z2 > 0.f ? z2 : 0.f;  z3 = z3 > 0.f ? z3 : 0.f;
            float2 r1 = *(const float2*)&in[(b*Cn + o1)*Ln + col];
            float2 r2 = *(const float2*)&in[(b*Cn + o2)*Ln + col];
            float v0 = r1.x + z0, v1 = r1.y + z1;
            float v2 = r2.x + z2, v3 = r2.y + z3;
            *(float2*)&out[(b*Cn + o1)*Ln + col] = make_float2(v0, v1);
            *(float2*)&out[(b*Cn + o2)*Ln + col] = make_float2(v2, v3);
            s  += v0 + v1 + v2 + v3;
            ss += v0*v0 + v1*v1 + v2*v2 + v3*v3;
        }
    }
    block_reduce2(s, ss, &partOut[(b*64 + lt)*2], red);
}

// ---------------- generic matmul ----------------
// grid (B, NLT64), block 256
#define MM_SMEM_F (9216 + 16)
template<bool LN, bool RELU, bool STATS>
__global__ __launch_bounds__(256, 4) void k_mm(
        const float* __restrict__ in, const float* resid, float* __restrict__ out,
        const float4* __restrict__ Wf, const float* __restrict__ bias,
        const float* __restrict__ partIn, float* __restrict__ partOut, int nparts){
    extern __shared__ float sm[];
    float* Xsm = sm;                 // [c][64] pitch 72
    float* red = sm + 9216;
    int b = blockIdx.x, lt = blockIdx.y, tid = threadIdx.x;
    int l0 = lt * LT64;
    if (LN) stats_from_parts(partIn, b, nparts, red);
    __syncthreads();
    float mu = 0.f, rs = 1.f;
    if (LN){ mu = red[0]; rs = red[1]; }
    for (int idx = tid; idx < Cn*LT64; idx += 256){
        int c = idx >> 6, j = idx & 63;
        int gl = l0 + j;
        float v = 0.f;
        if (gl < Ln){
            v = in[(b*Cn + c)*Ln + gl];
            if (LN){
                float2 gb = g_ln2[c*Ln + gl];
                float a = rs*gb.x;
                v = fmaf(v, a, fmaf(-mu, a, gb.y));
            }
        }
        Xsm[c*72 + j] = to_tf32(v);
    }
    __syncthreads();

    GEMM_MMA8(Wf, Xsm, 72)

    int mo = w*16;
    float s = 0.f, ss = 0.f;
    #pragma unroll
    for (int nt = 0; nt < 8; nt++){
        int col = l0 + nt*8 + 2*cq;
        if (col < Ln){
            int o1 = mo + r, o2 = o1 + 8;
            float b1v = bias[o1], b2v = bias[o2];
            float z0 = acc[nt][0] + b1v, z1 = acc[nt][1] + b1v;
            float z2 = acc[nt][2] + b2v, z3 = acc[nt][3] + b2v;
            if (RELU){
                z0 = z0 > 0.f ? z0 : 0.f;  z1 = z1 > 0.f ? z1 : 0.f;
                z2 = z2 > 0.f ? z2 : 0.f;  z3 = z3 > 0.f ? z3 : 0.f;
            }
            float2 r1 = *(const float2*)&resid[(b*Cn + o1)*Ln + col];
            float2 r2 = *(const float2*)&resid[(b*Cn + o2)*Ln + col];
            float v0 = r1.x + z0, v1 = r1.y + z1;
            float v2 = r2.x + z2, v3 = r2.y + z3;
            *(float2*)&out[(b*Cn + o1)*Ln + col] = make_float2(v0, v1);
            *(float2*)&out[(b*Cn + o2)*Ln + col] = make_float2(v2, v3);
            if (STATS){
                s  += v0 + v1 + v2 + v3;
                ss += v0*v0 + v1*v1 + v2*v2 + v3*v3;
            }
        }
    }
    if (STATS) block_reduce2(s, ss, &partOut[(b*64 + lt)*2], red);
}

// ---------------- merged QKV v2: LT64, stage X once, 3 sequential A-streams ----------------
// grid (B, NLT64), block 256 ; X [c][64] pitch 72
#define QKV_SMEM_F (9216 + 16)
__global__ __launch_bounds__(256, 3) void k_qkv(
        const float* __restrict__ in,
        const float* __restrict__ bq_s, const float* __restrict__ bk,
        const float* __restrict__ bv,
        const float* __restrict__ partIn, int nparts){
    extern __shared__ float sm[];
    float* Xsm = sm;                 // [c][64] pitch 72
    float* red = sm + 9216;
    int b = blockIdx.x, lt = blockIdx.y, tid = threadIdx.x;
    int l0 = lt * LT64;
    stats_from_parts(partIn, b, nparts, red);
    __syncthreads();
    float mu = red[0], rs = red[1];
    for (int idx = tid; idx < Cn*LT64; idx += 256){
        int c = idx >> 6, j = idx & 63;
        int gl = l0 + j;
        float v = 0.f;
        if (gl < Ln){
            float2 gb = g_ln2[c*Ln + gl];
            float a = rs*gb.x;
            v = fmaf(in[(b*Cn + c)*Ln + gl], a, fmaf(-mu, a, gb.y));
        }
        Xsm[c*72 + j] = to_tf32(v);
    }
    __syncthreads();

    int lane = tid & 31, w = tid >> 5;
    int r = lane >> 2, cq = lane & 3;
    #pragma unroll
    for (int m = 0; m < 3; m++){
        const float4* af = g_wfrag + (4 + m)*4096 + w*512 + lane;
        float acc[8][4];
        #pragma unroll
        for (int nt = 0; nt < 8; nt++){
            acc[nt][0] = 0.f; acc[nt][1] = 0.f; acc[nt][2] = 0.f; acc[nt][3] = 0.f;
        }
        #pragma unroll
        for (int k = 0; k < 16; k++){
            float4 a = af[k*32];
            const float* xb = Xsm + (k*8 + cq)*72 + r;
            #pragma unroll
            for (int nt = 0; nt < 8; nt++){
                mma_tf32(acc[nt], a, xb[nt*8], xb[4*72 + nt*8]);
            }
        }
        const float* bias = (m == 0) ? bq_s : (m == 1) ? bk : bv;
        float* outp       = (m == 0) ? g_q  : (m == 1) ? g_k : g_v;
        int o1 = w*16 + r, o2 = o1 + 8;
        float b1v = bias[o1], b2v = bias[o2];
        #pragma unroll
        for (int nt = 0; nt < 8; nt++){
            int col = l0 + nt*8 + 2*cq;
            if (col < Ln){
                float* p = outp + ((size_t)(b*Hn + w)*Ln + col)*16;
                p[r]          = acc[nt][0] + b1v;
                p[16 + r]     = acc[nt][1] + b1v;
                p[r + 8]      = acc[nt][2] + b2v;
                p[16 + r + 8] = acc[nt][3] + b2v;
            }
        }
    }
}

// ---------------- attention: flash-style tf32 mma ----------------
#define ATTN_K_P 20
#define ATTN_V_P 24
#define ATTN_P_P 44
#define ATTN_SMEM_F (Ln*ATTN_K_P + Ln*ATTN_V_P + Ln + 8*16*ATTN_P_P)
__global__ __launch_bounds__(256, 2) void k_attn(const float* __restrict__ mask){
    extern __shared__ float sm[];
    float* Ksm = sm;                                  // pitch 20
    float* Vsm = sm + Ln*ATTN_K_P;                    // pitch 24
    float* Msm = Vsm + Ln*ATTN_V_P;
    float* Pall = Msm + Ln;
    int bh = blockIdx.x;
    int b = bh >> 3, h = bh & 7;
    int tid = threadIdx.x;
    {
        const float4* kp = (const float4*)(g_k + (size_t)bh*Ln*16);
        const float4* vp = (const float4*)(g_v + (size_t)bh*Ln*16);
        for (int i = tid; i < Ln*4; i += 256){
            int row = i >> 2, q = i & 3;
            float4 kv = kp[i];
            kv.x = to_tf32(kv.x); kv.y = to_tf32(kv.y);
            kv.z = to_tf32(kv.z); kv.w = to_tf32(kv.w);
            *(float4*)(Ksm + row*ATTN_K_P + q*4) = kv;
            float4 vv = vp[i];
            vv.x = to_tf32(vv.x); vv.y = to_tf32(vv.y);
            vv.z = to_tf32(vv.z); vv.w = to_tf32(vv.w);
            *(float4*)(Vsm + row*ATTN_V_P + q*4) = vv;
        }
        for (int i = tid; i < Ln; i += 256) Msm[i] = mask[b*Ln + i];
    }
    __syncthreads();

    int lane = tid & 31, w = tid >> 5;
    int r = lane >> 2, cq = lane & 3;
    float* Pw = Pall + w*16*ATTN_P_P;
    const float* Qbase = g_q + (size_t)bh*Ln*16;
    size_t obase = ((size_t)b*Cn + h*16)*Ln;

    for (int mt = w; mt < 25; mt += 8){
        int mo = mt*16;
        float4 qf0, qf1;
        qf0.x = to_tf32(Qbase[(mo + r    )*16 + cq    ]);
        qf0.y = to_tf32(Qbase[(mo + r + 8)*16 + cq    ]);
        qf0.z = to_tf32(Qbase[(mo + r    )*16 + cq + 4]);
        qf0.w = to_tf32(Qbase[(mo + r + 8)*16 + cq + 4]);
        qf1.x = to_tf32(Qbase[(mo + r    )*16 + 8 + cq    ]);
        qf1.y = to_tf32(Qbase[(mo + r + 8)*16 + 8 + cq    ]);
        qf1.z = to_tf32(Qbase[(mo + r    )*16 + 8 + cq + 4]);
        qf1.w = to_tf32(Qbase[(mo + r + 8)*16 + 8 + cq + 4]);

        float m0 = -3.0e38f, m1 = -3.0e38f, den0 = 0.f, den1 = 0.f;
        float oa[2][4];
        oa[0][0]=oa[0][1]=oa[0][2]=oa[0][3]=0.f;
        oa[1][0]=oa[1][1]=oa[1][2]=oa[1][3]=0.f;

        for (int kc = 0; kc < Ln; kc += 40){
            float sc[5][4];
            #pragma unroll
            for (int st = 0; st < 5; st++){
                sc[st][0]=0.f; sc[st][1]=0.f; sc[st][2]=0.f; sc[st][3]=0.f;
                const float* kb = Ksm + (kc + st*8 + r)*ATTN_K_P + cq;
                mma_tf32(sc[st], qf0, kb[0], kb[4]);
                mma_tf32(sc[st], qf1, kb[8], kb[12]);
            }
            #pragma unroll
            for (int st = 0; st < 5; st++){
                float2 mk = *(const float2*)(Msm + kc + st*8 + 2*cq);
                float a0 = (1.f - mk.x)*(-1e30f), a1 = (1.f - mk.y)*(-1e30f);
                sc[st][0] = sc[st][0]*mk.x + a0;
                sc[st][1] = sc[st][1]*mk.y + a1;
                sc[st][2] = sc[st][2]*mk.x + a0;
                sc[st][3] = sc[st][3]*mk.y + a1;
            }
            float cm0 = -3.0e38f, cm1 = -3.0e38f;
            #pragma unroll
            for (int st = 0; st < 5; st++){
                cm0 = fmaxf(cm0, fmaxf(sc[st][0], sc[st][1]));
                cm1 = fmaxf(cm1, fmaxf(sc[st][2], sc[st][3]));
            }
            cm0 = fmaxf(cm0, __shfl_xor_sync(0xffffffffu, cm0, 1));
            cm0 = fmaxf(cm0, __shfl_xor_sync(0xffffffffu, cm0, 2));
            cm1 = fmaxf(cm1, __shfl_xor_sync(0xffffffffu, cm1, 1));
            cm1 = fmaxf(cm1, __shfl_xor_sync(0xffffffffu, cm1, 2));
            float nm0 = fmaxf(m0, cm0), nm1 = fmaxf(m1, cm1);
            float f0 = __expf(m0 - nm0), f1 = __expf(m1 - nm1);
            m0 = nm0; m1 = nm1;
            den0 *= f0; den1 *= f1;
            #pragma unroll
            for (int nt = 0; nt < 2; nt++){
                oa[nt][0] *= f0; oa[nt][1] *= f0;
                oa[nt][2] *= f1; oa[nt][3] *= f1;
            }
            #pragma unroll
            for (int st = 0; st < 5; st++){
                float p0 = __expf(sc[st][0] - m0);
                float p1 = __expf(sc[st][1] - m0);
                float p2 = __expf(sc[st][2] - m1);
                float p3 = __expf(sc[st][3] - m1);
                den0 += p0 + p1; den1 += p2 + p3;
                *(float2*)(Pw + r*ATTN_P_P + st*8 + 2*cq)     = make_float2(to_tf32(p0), to_tf32(p1));
                *(float2*)(Pw + (r+8)*ATTN_P_P + st*8 + 2*cq) = make_float2(to_tf32(p2), to_tf32(p3));
            }
            __syncwarp();
            #pragma unroll
            for (int kf = 0; kf < 5; kf++){
                float4 a;
                a.x = Pw[r*ATTN_P_P + kf*8 + cq];
                a.y = Pw[(r+8)*ATTN_P_P + kf*8 + cq];
                a.z = Pw[r*ATTN_P_P + kf*8 + cq + 4];
                a.w = Pw[(r+8)*ATTN_P_P + kf*8 + cq + 4];
                const float* vb  = Vsm + (kc + kf*8 + cq    )*ATTN_V_P + r;
                const float* vb4 = Vsm + (kc + kf*8 + cq + 4)*ATTN_V_P + r;
                mma_tf32(oa[0], a, vb[0], vb4[0]);
                mma_tf32(oa[1], a, vb[8], vb4[8]);
            }
            __syncwarp();
        }
        den0 += __shfl_xor_sync(0xffffffffu, den0, 1);
        den0 += __shfl_xor_sync(0xffffffffu, den0, 2);
        den1 += __shfl_xor_sync(0xffffffffu, den1, 1);
        den1 += __shfl_xor_sync(0xffffffffu, den1, 2);
        float i0 = 1.f/den0, i1 = 1.f/den1;
        int row0 = mo + r, row1 = mo + r + 8;
        #pragma unroll
        for (int nt = 0; nt < 2; nt++){
            int d0 = nt*8 + 2*cq;
            g_scr[obase + (size_t)d0*Ln + row0]     = oa[nt][0]*i0;
            g_scr[obase + (size_t)(d0+1)*Ln + row0] = oa[nt][1]*i0;
            g_scr[obase + (size_t)d0*Ln + row1]     = oa[nt][2]*i1;
            g_scr[obase + (size_t)(d0+1)*Ln + row1] = oa[nt][3]*i1;
        }
    }
}

// ---------------- host launcher ----------------
extern "C" void kernel_launch(void* const* d_in, const int* in_sizes, int n_in,
                              void* d_out, int out_size){
    (void)in_sizes; (void)n_in; (void)out_size;
    const float* x    = (const float*)d_in[0];
    const float* mask = (const float*)d_in[1];
    const float* dw_w = (const float*)d_in[2];
    const float* dw_b = (const float*)d_in[3];
    const float* pw_w = (const float*)d_in[4];
    const float* pw_b = (const float*)d_in[5];
    const float* wq   = (const float*)d_in[6];
    const float* bq   = (const float*)d_in[7];
    const float* wk   = (const float*)d_in[8];
    const float* bk   = (const float*)d_in[9];
    const float* wv   = (const float*)d_in[10];
    const float* bv   = (const float*)d_in[11];
    const float* wo   = (const float*)d_in[12];
    const float* bo   = (const float*)d_in[13];
    const float* fc_w = (const float*)d_in[14];
    const float* fc_b = (const float*)d_in[15];
    const float* ln_g = (const float*)d_in[16];
    const float* ln_b = (const float*)d_in[17];
    float* outp = (float*)d_out;

    float *bufA, *bufB, *scr, *pA, *pB, *bqs;
    float4* wf;
    cudaGetSymbolAddress((void**)&bufA, g_bufA);
    cudaGetSymbolAddress((void**)&bufB, g_bufB);
    cudaGetSymbolAddress((void**)&scr,  g_scr);
    cudaGetSymbolAddress((void**)&pA,   g_partA);
    cudaGetSymbolAddress((void**)&pB,   g_partB);
    cudaGetSymbolAddress((void**)&wf,   g_wfrag);
    cudaGetSymbolAddress((void**)&bqs,  g_bqs);

    const int CONV_SMEM = CONV_SMEM_F * 4;
    const int MM_SMEM   = MM_SMEM_F * 4;
    const int QKV_SMEM  = QKV_SMEM_F * 4;
    const int ATTN_SMEM = ATTN_SMEM_F * 4;
    cudaFuncSetAttribute(k_attn, cudaFuncAttributeMaxDynamicSharedMemorySize, ATTN_SMEM);

    // stage 0: weight fragment packing + ln pack + pos table
    k_prep<<<(CLn + 255)/256, 256>>>(pw_w, wq, wk, wv, wo, fc_w, bq, ln_g, ln_b);

    // stage 1: x + pos (table add), LN partials -> pA
    k_pos<<<dim3(Bn, 50), 256>>>(x);

    // stage 2: 4 fused conv layers
    float* cin  = bufA;
    float* cout = bufB;
    const float* pin = pA;
    float* pout = pB;
    int nparts = 50;
    for (int i = 0; i < 4; i++){
        k_conv<<<dim3(Bn, NLT64), 256, CONV_SMEM>>>(cin, cout,
            wf + i*4096, dw_w + i*Cn*Kn, dw_b + i*Cn, pw_b + i*Cn,
            pin, pout, nparts);
        float* t = cin; cin = cout; cout = t;
        float* tp = (float*)pin; pin = pout; pout = tp;
        nparts = NLT64;
    }
    // cin = residual after 4 conv layers; partials in pin (nparts=7)

    // stage 3: attention
    k_qkv<<<dim3(Bn, NLT64), 256, QKV_SMEM>>>(cin, bqs, bk, bv, pin, nparts);
    k_attn<<<Bn*Hn, 256, ATTN_SMEM>>>(mask);
    k_mm<false,false,true><<<dim3(Bn, NLT64), 256, MM_SMEM>>>(scr, cin, cout,
        wf + 7*4096, bo, nullptr, pout, 0);

    // stage 4: FC + relu + residual -> final output
    k_mm<true,true,false><<<dim3(Bn, NLT64), 256, MM_SMEM>>>(cout, cout, outp,
        wf + 8*4096, fc_b, pout, nullptr, NLT64);
}

// round 16
// speedup vs baseline: 1.0185x; 1.0090x over previous
#include <cuda_runtime.h>

#define Bn 64
#define Cn 128
#define Ln 400
#define Hn 8
#define Kn 7
#define CLn (Cn*Ln)            // 51200
#define BCL (Bn*Cn*Ln)         // 3276800
#define EPSf 1e-5f
#define LT64 64
#define NLT64 7
#define QSCALE 0.08838834764831845f

// ---------------- scratch ----------------
__device__ float g_bufA[BCL];
__device__ float g_bufB[BCL];
__device__ float g_scr[BCL];     // attention output (B,C,L)
__device__ float g_q[BCL];       // (B,H,L,DK)
__device__ float g_k[BCL];
__device__ float g_v[BCL];
__device__ float g_partA[Bn*64*2];
__device__ float g_partB[Bn*64*2];
__device__ float4 g_wfrag[9*4096]; // mma A-fragments: [m][w(8)][k(16)][lane(32)]
__device__ float g_bqs[Cn];
__device__ float2 g_ln2[CLn];

// ---------------- helpers ----------------
typedef unsigned long long u64;
__device__ __forceinline__ float to_tf32(float x){
    unsigned u; asm("cvt.rna.tf32.f32 %0, %1;" : "=r"(u) : "f"(x));
    return __uint_as_float(u);
}
__device__ __forceinline__ void mma_tf32(float* c, float4 a, float b0, float b1){
    asm volatile("mma.sync.aligned.m16n8k8.row.col.f32.tf32.tf32.f32 "
        "{%0,%1,%2,%3}, {%4,%5,%6,%7}, {%8,%9}, {%0,%1,%2,%3};"
        : "+f"(c[0]), "+f"(c[1]), "+f"(c[2]), "+f"(c[3])
        : "r"(__float_as_uint(a.x)), "r"(__float_as_uint(a.y)),
          "r"(__float_as_uint(a.z)), "r"(__float_as_uint(a.w)),
          "r"(__float_as_uint(b0)), "r"(__float_as_uint(b1)));
}

__device__ __forceinline__ void block_reduce2(float s, float ss, float* out2, float* red){
    #pragma unroll
    for (int o = 16; o > 0; o >>= 1){
        s  += __shfl_down_sync(0xffffffffu, s,  o);
        ss += __shfl_down_sync(0xffffffffu, ss, o);
    }
    int w = threadIdx.x >> 5;
    if ((threadIdx.x & 31) == 0){ red[w*2] = s; red[w*2+1] = ss; }
    __syncthreads();
    if (threadIdx.x == 0){
        float a = 0.f, b = 0.f;
        int nw = blockDim.x >> 5;
        for (int i = 0; i < nw; i++){ a += red[i*2]; b += red[i*2+1]; }
        out2[0] = a; out2[1] = b;
    }
}

__device__ __forceinline__ void stats_from_parts(const float* partIn, int b, int nparts, float* red){
    if (threadIdx.x < 32){
        float s = 0.f, ss = 0.f;
        for (int i = threadIdx.x; i < nparts; i += 32){
            s  += partIn[(b*64+i)*2];
            ss += partIn[(b*64+i)*2+1];
        }
        #pragma unroll
        for (int o = 16; o > 0; o >>= 1){
            s  += __shfl_down_sync(0xffffffffu, s,  o);
            ss += __shfl_down_sync(0xffffffffu, ss, o);
        }
        if (threadIdx.x == 0){
            float mu  = s / (float)CLn;
            float var = ss / (float)CLn - mu*mu;
            red[0] = mu;
            red[1] = rsqrtf(var + EPSf);
        }
    }
}

// ---------------- merged pos + prep ----------------
// grid (Bn, 50), block 256. All blocks do pos (x + sin table add + LN partials).
// Blocks with gid = bx*50+by < 200 additionally do prep (wfrag + ln2 + bqs).
__global__ __launch_bounds__(256) void k_pos(const float* __restrict__ x,
        const float* __restrict__ pw, const float* __restrict__ wq,
        const float* __restrict__ wk, const float* __restrict__ wv,
        const float* __restrict__ wo, const float* __restrict__ fcw,
        const float* __restrict__ bq,
        const float* __restrict__ lng, const float* __restrict__ lnb){
    __shared__ float fr[Cn], phs[Cn];
    __shared__ float red[16];
    int tid = threadIdx.x;
    if (tid < Cn){
        int c = tid;
        if ((c & 1) == 0){ fr[c] =  powf(10000.f, -(float)c/128.f);       phs[c] = 0.f; }
        else             { fr[c] = -powf(10000.f, (1.f-(float)c)/128.f);  phs[c] = 1.5707963267948966f; }
    }
    __syncthreads();
    int b  = blockIdx.x;
    int i4 = blockIdx.y * 256 + tid;
    float4 xv = ((const float4*)x)[b*(CLn/4) + i4];
    int e0 = i4 * 4;
    int c  = e0 / Ln;
    int l  = e0 - c * Ln;
    float fc = fr[c], ph = phs[c];
    float v0 = xv.x + sinf((float)(l+0)*fc + ph);
    float v1 = xv.y + sinf((float)(l+1)*fc + ph);
    float v2 = xv.z + sinf((float)(l+2)*fc + ph);
    float v3 = xv.w + sinf((float)(l+3)*fc + ph);
    ((float4*)g_bufA)[b*(CLn/4) + i4] = make_float4(v0, v1, v2, v3);
    float s  = v0 + v1 + v2 + v3;
    float ss = v0*v0 + v1*v1 + v2*v2 + v3*v3;
    block_reduce2(s, ss, &g_partA[(b*64 + blockIdx.y)*2], red);

    // prep duty for first 200 block-ids
    int gid = b*50 + blockIdx.y;
    if (gid < 200){
        int idx = gid*256 + tid;
        if (idx < 9*4096){
            int m = idx >> 12;
            int rest = idx & 4095;
            int w = rest >> 9;
            int k = (rest >> 5) & 15;
            int lane = rest & 31;
            int r = lane >> 2, cq = lane & 3;
            const float* src = (m < 4) ? (pw + m*Cn*Cn) :
                               (m == 4) ? wq : (m == 5) ? wk : (m == 6) ? wv :
                               (m == 7) ? wo : fcw;
            float sc = (m == 4) ? QSCALE : 1.f;
            int mo = w*16, c0 = k*8;
            float a0 = to_tf32(src[(mo + r    )*Cn + c0 + cq    ] * sc);
            float a1 = to_tf32(src[(mo + r + 8)*Cn + c0 + cq    ] * sc);
            float a2 = to_tf32(src[(mo + r    )*Cn + c0 + cq + 4] * sc);
            float a3 = to_tf32(src[(mo + r + 8)*Cn + c0 + cq + 4] * sc);
            g_wfrag[idx] = make_float4(a0, a1, a2, a3);
        }
        if (idx < CLn) g_ln2[idx] = make_float2(lng[idx], lnb[idx]);
        if (idx < Cn) g_bqs[idx] = bq[idx] * QSCALE;
    }
}

// ===== GEMM mainloop, 8 n-tiles (64 cols), pitch P (P mod 32 == 8 -> conflict-free) =====
#define GEMM_MMA8(WFp, XS, P)                                                   \
    int lane = tid & 31, w = tid >> 5;                                          \
    int r = lane >> 2, cq = lane & 3;                                           \
    float acc[8][4];                                                            \
    _Pragma("unroll")                                                           \
    for (int nt = 0; nt < 8; nt++){                                             \
        acc[nt][0] = 0.f; acc[nt][1] = 0.f; acc[nt][2] = 0.f; acc[nt][3] = 0.f; \
    }                                                                           \
    {                                                                           \
        const float4* af = (WFp) + w*512 + lane;                                \
        _Pragma("unroll")                                                       \
        for (int k = 0; k < 16; k++){                                           \
            float4 a = af[k*32];                                                \
            const float* xb = (XS) + (k*8 + cq)*(P) + r;                        \
            _Pragma("unroll")                                                   \
            for (int nt = 0; nt < 8; nt++){                                     \
                mma_tf32(acc[nt], a, xb[nt*8], xb[4*(P) + nt*8]);               \
            }                                                                   \
        }                                                                       \
    }

// ---------------- fused conv layer ----------------
// grid (B, NLT64), block 256
// smem: XsmH [c][70] pitch 72 (x halo; depthwise writes y[c][l] to index l+6 in-place)
#define CONV_SMEM_F (9216 + 1024 + 128 + 16)
__global__ __launch_bounds__(256, 4) void k_conv(
        const float* __restrict__ in, float* __restrict__ out,
        const float4* __restrict__ Wf,
        const float* __restrict__ dw, const float* __restrict__ db,
        const float* __restrict__ pb,
        const float* __restrict__ partIn, float* __restrict__ partOut, int nparts){
    extern __shared__ float sm[];
    float* XsmH = sm;                  // [c][70] pitch 72 ; y aliased at +6
    float* Dw   = sm + 9216;
    float* Db   = Dw + 1024;
    float* red  = Db + 128;
    int b = blockIdx.x, lt = blockIdx.y, tid = threadIdx.x;
    int l0 = lt * LT64;

    stats_from_parts(partIn, b, nparts, red);
    for (int idx = tid; idx < Cn*Kn; idx += 256)
        Dw[(idx/7)*8 + (idx - (idx/7)*7)] = dw[idx];
    if (tid < Cn) Db[tid] = db[tid];
    __syncthreads();
    float mu = red[0], rs = red[1];
    // main stage: 64 cols at row offset +3 (shift-based indexing, coalesced)
    #pragma unroll
    for (int k = 0; k < 32; k++){
        int idx = k*256 + tid;
        int c = idx >> 6, j = idx & 63;
        int gl = l0 + j;
        float v = 0.f;
        if (gl < Ln){
            float2 gb = g_ln2[c*Ln + gl];
            float a = rs*gb.x;
            v = fmaf(in[(b*Cn + c)*Ln + gl], a, fmaf(-mu, a, gb.y));
        }
        XsmH[c*72 + 3 + j] = v;
    }
    // halo stage: 6 cols per row (left 3 at offsets 0..2, right 3 at 67..69)
    #pragma unroll
    for (int k = 0; k < 3; k++){
        int idx = k*256 + tid;            // 0..767
        int c = idx & 127, h = idx >> 7;  // h 0..5
        int pos = (h < 3) ? h : (64 + h); // 0,1,2,67,68,69
        int gl = l0 - 3 + pos;
        float v = 0.f;
        if (gl >= 0 && gl < Ln){
            float2 gb = g_ln2[c*Ln + gl];
            float a = rs*gb.x;
            v = fmaf(in[(b*Cn + c)*Ln + gl], a, fmaf(-mu, a, gb.y));
        }
        XsmH[c*72 + pos] = v;
    }
    __syncthreads();
    // depthwise in-place: y[c][l] -> index l+6 (the x cell read in the same iteration)
    {
        int c  = tid >> 1;
        int lb = (tid & 1) * 32;
        float* xr = XsmH + c*72 + lb;
        float d0 = Dw[c*8+0], d1 = Dw[c*8+1], d2 = Dw[c*8+2], d3 = Dw[c*8+3];
        float d4 = Dw[c*8+4], d5 = Dw[c*8+5], d6 = Dw[c*8+6];
        float bias = Db[c];
        float w0 = xr[0], w1 = xr[1], w2 = xr[2], w3 = xr[3], w4 = xr[4], w5 = xr[5];
        __syncwarp();   // all preloads (x[lb..lb+5]) before any in-place writes
        #pragma unroll
        for (int l = 0; l < 32; l++){
            float w6 = xr[l + 6];
            float a = bias;
            a = fmaf(w0, d0, a); a = fmaf(w1, d1, a); a = fmaf(w2, d2, a);
            a = fmaf(w3, d3, a); a = fmaf(w4, d4, a); a = fmaf(w5, d5, a);
            a = fmaf(w6, d6, a);
            xr[l + 6] = to_tf32(a);          // overwrite the cell just read
            w0 = w1; w1 = w2; w2 = w3; w3 = w4; w4 = w5; w5 = w6;
        }
    }
    __syncthreads();

    GEMM_MMA8(Wf, XsmH + 6, 72)

    int mo = w*16;
    float s = 0.f, ss = 0.f;
    #pragma unroll
    for (int nt = 0; nt < 8; nt++){
        int col = l0 + nt*8 + 2*cq;
        if (col < Ln){
            int o1 = mo + r, o2 = o1 + 8;
            float b1v = pb[o1], b2v = pb[o2];
            float z0 = acc[nt][0] + b1v, z1 = acc[nt][1] + b1v;
            float z2 = acc[nt][2] + b2v, z3 = acc[nt][3] + b2v;
            z0 = z0 > 0.f ? z0 : 0.f;  z1 = z1 > 0.f ? z1 : 0.f;
            z2 = z2 > 0.f ? z2 : 0.f;  z3 = z3 > 0.f ? z3 : 0.f;
            float2 r1 = *(const float2*)&in[(b*Cn + o1)*Ln + col];
            float2 r2 = *(const float2*)&in[(b*Cn + o2)*Ln + col];
            float v0 = r1.x + z0, v1 = r1.y + z1;
            float v2 = r2.x + z2, v3 = r2.y + z3;
            *(float2*)&out[(b*Cn + o1)*Ln + col] = make_float2(v0, v1);
            *(float2*)&out[(b*Cn + o2)*Ln + col] = make_float2(v2, v3);
            s  += v0 + v1 + v2 + v3;
            ss += v0*v0 + v1*v1 + v2*v2 + v3*v3;
        }
    }
    block_reduce2(s, ss, &partOut[(b*64 + lt)*2], red);
}

// ---------------- generic matmul ----------------
// grid (B, NLT64), block 256
#define MM_SMEM_F (9216 + 16)
template<bool LN, bool RELU, bool STATS>
__global__ __launch_bounds__(256, 4) void k_mm(
        const float* __restrict__ in, const float* resid, float* __restrict__ out,
        const float4* __restrict__ Wf, const float* __restrict__ bias,
        const float* __restrict__ partIn, float* __restrict__ partOut, int nparts){
    extern __shared__ float sm[];
    float* Xsm = sm;                 // [c][64] pitch 72
    float* red = sm + 9216;
    int b = blockIdx.x, lt = blockIdx.y, tid = threadIdx.x;
    int l0 = lt * LT64;
    if (LN) stats_from_parts(partIn, b, nparts, red);
    __syncthreads();
    float mu = 0.f, rs = 1.f;
    if (LN){ mu = red[0]; rs = red[1]; }
    for (int idx = tid; idx < Cn*LT64; idx += 256){
        int c = idx >> 6, j = idx & 63;
        int gl = l0 + j;
        float v = 0.f;
        if (gl < Ln){
            v = in[(b*Cn + c)*Ln + gl];
            if (LN){
                float2 gb = g_ln2[c*Ln + gl];
                float a = rs*gb.x;
                v = fmaf(v, a, fmaf(-mu, a, gb.y));
            }
        }
        Xsm[c*72 + j] = to_tf32(v);
    }
    __syncthreads();

    GEMM_MMA8(Wf, Xsm, 72)

    int mo = w*16;
    float s = 0.f, ss = 0.f;
    #pragma unroll
    for (int nt = 0; nt < 8; nt++){
        int col = l0 + nt*8 + 2*cq;
        if (col < Ln){
            int o1 = mo + r, o2 = o1 + 8;
            float b1v = bias[o1], b2v = bias[o2];
            float z0 = acc[nt][0] + b1v, z1 = acc[nt][1] + b1v;
            float z2 = acc[nt][2] + b2v, z3 = acc[nt][3] + b2v;
            if (RELU){
                z0 = z0 > 0.f ? z0 : 0.f;  z1 = z1 > 0.f ? z1 : 0.f;
                z2 = z2 > 0.f ? z2 : 0.f;  z3 = z3 > 0.f ? z3 : 0.f;
            }
            float2 r1 = *(const float2*)&resid[(b*Cn + o1)*Ln + col];
            float2 r2 = *(const float2*)&resid[(b*Cn + o2)*Ln + col];
            float v0 = r1.x + z0, v1 = r1.y + z1;
            float v2 = r2.x + z2, v3 = r2.y + z3;
            *(float2*)&out[(b*Cn + o1)*Ln + col] = make_float2(v0, v1);
            *(float2*)&out[(b*Cn + o2)*Ln + col] = make_float2(v2, v3);
            if (STATS){
                s  += v0 + v1 + v2 + v3;
                ss += v0*v0 + v1*v1 + v2*v2 + v3*v3;
            }
        }
    }
    if (STATS) block_reduce2(s, ss, &partOut[(b*64 + lt)*2], red);
}

// ---------------- merged QKV: LT64, stage X once, 3 sequential A-streams ----------------
// grid (B, NLT64), block 256 ; X [c][64] pitch 72
#define QKV_SMEM_F (9216 + 16)
__global__ __launch_bounds__(256, 3) void k_qkv(
        const float* __restrict__ in,
        const float* __restrict__ bq_s, const float* __restrict__ bk,
        const float* __restrict__ bv,
        const float* __restrict__ partIn, int nparts){
    extern __shared__ float sm[];
    float* Xsm = sm;                 // [c][64] pitch 72
    float* red = sm + 9216;
    int b = blockIdx.x, lt = blockIdx.y, tid = threadIdx.x;
    int l0 = lt * LT64;
    stats_from_parts(partIn, b, nparts, red);
    __syncthreads();
    float mu = red[0], rs = red[1];
    for (int idx = tid; idx < Cn*LT64; idx += 256){
        int c = idx >> 6, j = idx & 63;
        int gl = l0 + j;
        float v = 0.f;
        if (gl < Ln){
            float2 gb = g_ln2[c*Ln + gl];
            float a = rs*gb.x;
            v = fmaf(in[(b*Cn + c)*Ln + gl], a, fmaf(-mu, a, gb.y));
        }
        Xsm[c*72 + j] = to_tf32(v);
    }
    __syncthreads();

    int lane = tid & 31, w = tid >> 5;
    int r = lane >> 2, cq = lane & 3;
    #pragma unroll
    for (int m = 0; m < 3; m++){
        const float4* af = g_wfrag + (4 + m)*4096 + w*512 + lane;
        float acc[8][4];
        #pragma unroll
        for (int nt = 0; nt < 8; nt++){
            acc[nt][0] = 0.f; acc[nt][1] = 0.f; acc[nt][2] = 0.f; acc[nt][3] = 0.f;
        }
        #pragma unroll
        for (int k = 0; k < 16; k++){
            float4 a = af[k*32];
            const float* xb = Xsm + (k*8 + cq)*72 + r;
            #pragma unroll
            for (int nt = 0; nt < 8; nt++){
                mma_tf32(acc[nt], a, xb[nt*8], xb[4*72 + nt*8]);
            }
        }
        const float* bias = (m == 0) ? bq_s : (m == 1) ? bk : bv;
        float* outp       = (m == 0) ? g_q  : (m == 1) ? g_k : g_v;
        int o1 = w*16 + r, o2 = o1 + 8;
        float b1v = bias[o1], b2v = bias[o2];
        #pragma unroll
        for (int nt = 0; nt < 8; nt++){
            int col = l0 + nt*8 + 2*cq;
            if (col < Ln){
                float* p = outp + ((size_t)(b*Hn + w)*Ln + col)*16;
                p[r]          = acc[nt][0] + b1v;
                p[16 + r]     = acc[nt][1] + b1v;
                p[r + 8]      = acc[nt][2] + b2v;
                p[16 + r + 8] = acc[nt][3] + b2v;
            }
        }
    }
}

// ---------------- attention: flash-style tf32 mma ----------------
#define ATTN_K_P 20
#define ATTN_V_P 24
#define ATTN_P_P 44
#define ATTN_SMEM_F (Ln*ATTN_K_P + Ln*ATTN_V_P + Ln + 8*16*ATTN_P_P)
__global__ __launch_bounds__(256, 2) void k_attn(const float* __restrict__ mask){
    extern __shared__ float sm[];
    float* Ksm = sm;                                  // pitch 20
    float* Vsm = sm + Ln*ATTN_K_P;                    // pitch 24
    float* Msm = Vsm + Ln*ATTN_V_P;
    float* Pall = Msm + Ln;
    int bh = blockIdx.x;
    int b = bh >> 3, h = bh & 7;
    int tid = threadIdx.x;
    {
        const float4* kp = (const float4*)(g_k + (size_t)bh*Ln*16);
        const float4* vp = (const float4*)(g_v + (size_t)bh*Ln*16);
        for (int i = tid; i < Ln*4; i += 256){
            int row = i >> 2, q = i & 3;
            float4 kv = kp[i];
            kv.x = to_tf32(kv.x); kv.y = to_tf32(kv.y);
            kv.z = to_tf32(kv.z); kv.w = to_tf32(kv.w);
            *(float4*)(Ksm + row*ATTN_K_P + q*4) = kv;
            float4 vv = vp[i];
            vv.x = to_tf32(vv.x); vv.y = to_tf32(vv.y);
            vv.z = to_tf32(vv.z); vv.w = to_tf32(vv.w);
            *(float4*)(Vsm + row*ATTN_V_P + q*4) = vv;
        }
        for (int i = tid; i < Ln; i += 256) Msm[i] = mask[b*Ln + i];
    }
    __syncthreads();

    int lane = tid & 31, w = tid >> 5;
    int r = lane >> 2, cq = lane & 3;
    float* Pw = Pall + w*16*ATTN_P_P;
    const float* Qbase = g_q + (size_t)bh*Ln*16;
    size_t obase = ((size_t)b*Cn + h*16)*Ln;

    for (int mt = w; mt < 25; mt += 8){
        int mo = mt*16;
        float4 qf0, qf1;
        qf0.x = to_tf32(Qbase[(mo + r    )*16 + cq    ]);
        qf0.y = to_tf32(Qbase[(mo + r + 8)*16 + cq    ]);
        qf0.z = to_tf32(Qbase[(mo + r    )*16 + cq + 4]);
        qf0.w = to_tf32(Qbase[(mo + r + 8)*16 + cq + 4]);
        qf1.x = to_tf32(Qbase[(mo + r    )*16 + 8 + cq    ]);
        qf1.y = to_tf32(Qbase[(mo + r + 8)*16 + 8 + cq    ]);
        qf1.z = to_tf32(Qbase[(mo + r    )*16 + 8 + cq + 4]);
        qf1.w = to_tf32(Qbase[(mo + r + 8)*16 + 8 + cq + 4]);

        float m0 = -3.0e38f, m1 = -3.0e38f, den0 = 0.f, den1 = 0.f;
        float oa[2][4];
        oa[0][0]=oa[0][1]=oa[0][2]=oa[0][3]=0.f;
        oa[1][0]=oa[1][1]=oa[1][2]=oa[1][3]=0.f;

        for (int kc = 0; kc < Ln; kc += 40){
            float sc[5][4];
            #pragma unroll
            for (int st = 0; st < 5; st++){
                sc[st][0]=0.f; sc[st][1]=0.f; sc[st][2]=0.f; sc[st][3]=0.f;
                const float* kb = Ksm + (kc + st*8 + r)*ATTN_K_P + cq;
                mma_tf32(sc[st], qf0, kb[0], kb[4]);
                mma_tf32(sc[st], qf1, kb[8], kb[12]);
            }
            #pragma unroll
            for (int st = 0; st < 5; st++){
                float2 mk = *(const float2*)(Msm + kc + st*8 + 2*cq);
                float a0 = (1.f - mk.x)*(-1e30f), a1 = (1.f - mk.y)*(-1e30f);
                sc[st][0] = sc[st][0]*mk.x + a0;
                sc[st][1] = sc[st][1]*mk.y + a1;
                sc[st][2] = sc[st][2]*mk.x + a0;
                sc[st][3] = sc[st][3]*mk.y + a1;
            }
            float cm0 = -3.0e38f, cm1 = -3.0e38f;
            #pragma unroll
            for (int st = 0; st < 5; st++){
                cm0 = fmaxf(cm0, fmaxf(sc[st][0], sc[st][1]));
                cm1 = fmaxf(cm1, fmaxf(sc[st][2], sc[st][3]));
            }
            cm0 = fmaxf(cm0, __shfl_xor_sync(0xffffffffu, cm0, 1));
            cm0 = fmaxf(cm0, __shfl_xor_sync(0xffffffffu, cm0, 2));
            cm1 = fmaxf(cm1, __shfl_xor_sync(0xffffffffu, cm1, 1));
            cm1 = fmaxf(cm1, __shfl_xor_sync(0xffffffffu, cm1, 2));
            float nm0 = fmaxf(m0, cm0), nm1 = fmaxf(m1, cm1);
            float f0 = __expf(m0 - nm0), f1 = __expf(m1 - nm1);
            m0 = nm0; m1 = nm1;
            den0 *= f0; den1 *= f1;
            #pragma unroll
            for (int nt = 0; nt < 2; nt++){
                oa[nt][0] *= f0; oa[nt][1] *= f0;
                oa[nt][2] *= f1; oa[nt][3] *= f1;
            }
            #pragma unroll
            for (int st = 0; st < 5; st++){
                float p0 = __expf(sc[st][0] - m0);
                float p1 = __expf(sc[st][1] - m0);
                float p2 = __expf(sc[st][2] - m1);
                float p3 = __expf(sc[st][3] - m1);
                den0 += p0 + p1; den1 += p2 + p3;
                *(float2*)(Pw + r*ATTN_P_P + st*8 + 2*cq)     = make_float2(to_tf32(p0), to_tf32(p1));
                *(float2*)(Pw + (r+8)*ATTN_P_P + st*8 + 2*cq) = make_float2(to_tf32(p2), to_tf32(p3));
            }
            __syncwarp();
            #pragma unroll
            for (int kf = 0; kf < 5; kf++){
                float4 a;
                a.x = Pw[r*ATTN_P_P + kf*8 + cq];
                a.y = Pw[(r+8)*ATTN_P_P + kf*8 + cq];
                a.z = Pw[r*ATTN_P_P + kf*8 + cq + 4];
                a.w = Pw[(r+8)*ATTN_P_P + kf*8 + cq + 4];
                const float* vb  = Vsm + (kc + kf*8 + cq    )*ATTN_V_P + r;
                const float* vb4 = Vsm + (kc + kf*8 + cq + 4)*ATTN_V_P + r;
                mma_tf32(oa[0], a, vb[0], vb4[0]);
                mma_tf32(oa[1], a, vb[8], vb4[8]);
            }
            __syncwarp();
        }
        den0 += __shfl_xor_sync(0xffffffffu, den0, 1);
        den0 += __shfl_xor_sync(0xffffffffu, den0, 2);
        den1 += __shfl_xor_sync(0xffffffffu, den1, 1);
        den1 += __shfl_xor_sync(0xffffffffu, den1, 2);
        float i0 = 1.f/den0, i1 = 1.f/den1;
        int row0 = mo + r, row1 = mo + r + 8;
        #pragma unroll
        for (int nt = 0; nt < 2; nt++){
            int d0 = nt*8 + 2*cq;
            g_scr[obase + (size_t)d0*Ln + row0]     = oa[nt][0]*i0;
            g_scr[obase + (size_t)(d0+1)*Ln + row0] = oa[nt][1]*i0;
            g_scr[obase + (size_t)d0*Ln + row1]     = oa[nt][2]*i1;
            g_scr[obase + (size_t)(d0+1)*Ln + row1] = oa[nt][3]*i1;
        }
    }
}

// ---------------- host launcher ----------------
extern "C" void kernel_launch(void* const* d_in, const int* in_sizes, int n_in,
                              void* d_out, int out_size){
    (void)in_sizes; (void)n_in; (void)out_size;
    const float* x    = (const float*)d_in[0];
    const float* mask = (const float*)d_in[1];
    const float* dw_w = (const float*)d_in[2];
    const float* dw_b = (const float*)d_in[3];
    const float* pw_w = (const float*)d_in[4];
    const float* pw_b = (const float*)d_in[5];
    const float* wq   = (const float*)d_in[6];
    const float* bq   = (const float*)d_in[7];
    const float* wk   = (const float*)d_in[8];
    const float* bk   = (const float*)d_in[9];
    const float* wv   = (const float*)d_in[10];
    const float* bv   = (const float*)d_in[11];
    const float* wo   = (const float*)d_in[12];
    const float* bo   = (const float*)d_in[13];
    const float* fc_w = (const float*)d_in[14];
    const float* fc_b = (const float*)d_in[15];
    const float* ln_g = (const float*)d_in[16];
    const float* ln_b = (const float*)d_in[17];
    float* outp = (float*)d_out;

    float *bufA, *bufB, *scr, *pA, *pB, *bqs;
    float4* wf;
    cudaGetSymbolAddress((void**)&bufA, g_bufA);
    cudaGetSymbolAddress((void**)&bufB, g_bufB);
    cudaGetSymbolAddress((void**)&scr,  g_scr);
    cudaGetSymbolAddress((void**)&pA,   g_partA);
    cudaGetSymbolAddress((void**)&pB,   g_partB);
    cudaGetSymbolAddress((void**)&wf,   g_wfrag);
    cudaGetSymbolAddress((void**)&bqs,  g_bqs);

    const int CONV_SMEM = CONV_SMEM_F * 4;
    const int MM_SMEM   = MM_SMEM_F * 4;
    const int QKV_SMEM  = QKV_SMEM_F * 4;
    const int ATTN_SMEM = ATTN_SMEM_F * 4;
    cudaFuncSetAttribute(k_attn, cudaFuncAttributeMaxDynamicSharedMemorySize, ATTN_SMEM);

    // stage 0+1: merged pos (+ prep duty on first 200 blocks), LN partials -> pA
    k_pos<<<dim3(Bn, 50), 256>>>(x, pw_w, wq, wk, wv, wo, fc_w, bq, ln_g, ln_b);

    // stage 2: 4 fused conv layers
    float* cin  = bufA;
    float* cout = bufB;
    const float* pin = pA;
    float* pout = pB;
    int nparts = 50;
    for (int i = 0; i < 4; i++){
        k_conv<<<dim3(Bn, NLT64), 256, CONV_SMEM>>>(cin, cout,
            wf + i*4096, dw_w + i*Cn*Kn, dw_b + i*Cn, pw_b + i*Cn,
            pin, pout, nparts);
        float* t = cin; cin = cout; cout = t;
        float* tp = (float*)pin; pin = pout; pout = tp;
        nparts = NLT64;
    }
    // cin = residual after 4 conv layers; partials in pin (nparts=7)

    // stage 3: attention
    k_qkv<<<dim3(Bn, NLT64), 256, QKV_SMEM>>>(cin, bqs, bk, bv, pin, nparts);
    k_attn<<<Bn*Hn, 256, ATTN_SMEM>>>(mask);
    k_mm<false,false,true><<<dim3(Bn, NLT64), 256, MM_SMEM>>>(scr, cin, cout,
        wf + 7*4096, bo, nullptr, pout, 0);

    // stage 4: FC + relu + residual -> final output
    k_mm<true,true,false><<<dim3(Bn, NLT64), 256, MM_SMEM>>>(cout, cout, outp,
        wf + 8*4096, fc_b, pout, nullptr, NLT64);
}

// round 17
// speedup vs baseline: 1.0448x; 1.0259x over previous
#include <cuda_runtime.h>

#define Bn 64
#define Cn 128
#define Ln 400
#define Hn 8
#define Kn 7
#define CLn (Cn*Ln)            // 51200
#define BCL (Bn*Cn*Ln)         // 3276800
#define EPSf 1e-5f
#define LT64 64
#define NLT64 7
#define QSCALE 0.08838834764831845f

// ---------------- scratch ----------------
__device__ float g_bufA[BCL];
__device__ float g_bufB[BCL];
__device__ float g_scr[BCL];     // attention output (B,C,L)
__device__ float g_q[BCL];       // (B,H,L,DK)
__device__ float g_k[BCL];
__device__ float g_v[BCL];
__device__ float g_partA[Bn*64*2];
__device__ float g_partB[Bn*64*2];
__device__ float4 g_wfrag[9*4096]; // mma A-fragments: [m][w(8)][k(16)][lane(32)]
__device__ float g_bqs[Cn];
__device__ float2 g_ln2[CLn];

// ---------------- helpers ----------------
typedef unsigned long long u64;
__device__ __forceinline__ float to_tf32(float x){
    unsigned u; asm("cvt.rna.tf32.f32 %0, %1;" : "=r"(u) : "f"(x));
    return __uint_as_float(u);
}
__device__ __forceinline__ void mma_tf32(float* c, float4 a, float b0, float b1){
    asm volatile("mma.sync.aligned.m16n8k8.row.col.f32.tf32.tf32.f32 "
        "{%0,%1,%2,%3}, {%4,%5,%6,%7}, {%8,%9}, {%0,%1,%2,%3};"
        : "+f"(c[0]), "+f"(c[1]), "+f"(c[2]), "+f"(c[3])
        : "r"(__float_as_uint(a.x)), "r"(__float_as_uint(a.y)),
          "r"(__float_as_uint(a.z)), "r"(__float_as_uint(a.w)),
          "r"(__float_as_uint(b0)), "r"(__float_as_uint(b1)));
}

__device__ __forceinline__ void block_reduce2(float s, float ss, float* out2, float* red){
    #pragma unroll
    for (int o = 16; o > 0; o >>= 1){
        s  += __shfl_down_sync(0xffffffffu, s,  o);
        ss += __shfl_down_sync(0xffffffffu, ss, o);
    }
    int w = threadIdx.x >> 5;
    if ((threadIdx.x & 31) == 0){ red[w*2] = s; red[w*2+1] = ss; }
    __syncthreads();
    if (threadIdx.x == 0){
        float a = 0.f, b = 0.f;
        int nw = blockDim.x >> 5;
        for (int i = 0; i < nw; i++){ a += red[i*2]; b += red[i*2+1]; }
        out2[0] = a; out2[1] = b;
    }
}

__device__ __forceinline__ void stats_from_parts(const float* partIn, int b, int nparts, float* red){
    if (threadIdx.x < 32){
        float s = 0.f, ss = 0.f;
        for (int i = threadIdx.x; i < nparts; i += 32){
            s  += partIn[(b*64+i)*2];
            ss += partIn[(b*64+i)*2+1];
        }
        #pragma unroll
        for (int o = 16; o > 0; o >>= 1){
            s  += __shfl_down_sync(0xffffffffu, s,  o);
            ss += __shfl_down_sync(0xffffffffu, ss, o);
        }
        if (threadIdx.x == 0){
            float mu  = s / (float)CLn;
            float var = ss / (float)CLn - mu*mu;
            red[0] = mu;
            red[1] = rsqrtf(var + EPSf);
        }
    }
}

// ---------------- merged pos + prep ----------------
// grid (Bn, 50), block 256. All blocks do pos (x + sin table add + LN partials).
// Blocks with gid = bx*50+by < 200 additionally do prep (wfrag + ln2 + bqs).
__global__ __launch_bounds__(256) void k_pos(const float* __restrict__ x,
        const float* __restrict__ pw, const float* __restrict__ wq,
        const float* __restrict__ wk, const float* __restrict__ wv,
        const float* __restrict__ wo, const float* __restrict__ fcw,
        const float* __restrict__ bq,
        const float* __restrict__ lng, const float* __restrict__ lnb){
    __shared__ float fr[Cn], phs[Cn];
    __shared__ float red[16];
    int tid = threadIdx.x;
    if (tid < Cn){
        int c = tid;
        if ((c & 1) == 0){ fr[c] =  powf(10000.f, -(float)c/128.f);       phs[c] = 0.f; }
        else             { fr[c] = -powf(10000.f, (1.f-(float)c)/128.f);  phs[c] = 1.5707963267948966f; }
    }
    __syncthreads();
    int b  = blockIdx.x;
    int i4 = blockIdx.y * 256 + tid;
    float4 xv = ((const float4*)x)[b*(CLn/4) + i4];
    int e0 = i4 * 4;
    int c  = e0 / Ln;
    int l  = e0 - c * Ln;
    float fc = fr[c], ph = phs[c];
    float v0 = xv.x + sinf((float)(l+0)*fc + ph);
    float v1 = xv.y + sinf((float)(l+1)*fc + ph);
    float v2 = xv.z + sinf((float)(l+2)*fc + ph);
    float v3 = xv.w + sinf((float)(l+3)*fc + ph);
    ((float4*)g_bufA)[b*(CLn/4) + i4] = make_float4(v0, v1, v2, v3);
    float s  = v0 + v1 + v2 + v3;
    float ss = v0*v0 + v1*v1 + v2*v2 + v3*v3;
    block_reduce2(s, ss, &g_partA[(b*64 + blockIdx.y)*2], red);

    // prep duty for first 200 block-ids
    int gid = b*50 + blockIdx.y;
    if (gid < 200){
        int idx = gid*256 + tid;
        if (idx < 9*4096){
            int m = idx >> 12;
            int rest = idx & 4095;
            int w = rest >> 9;
            int k = (rest >> 5) & 15;
            int lane = rest & 31;
            int r = lane >> 2, cq = lane & 3;
            const float* src = (m < 4) ? (pw + m*Cn*Cn) :
                               (m == 4) ? wq : (m == 5) ? wk : (m == 6) ? wv :
                               (m == 7) ? wo : fcw;
            float sc = (m == 4) ? QSCALE : 1.f;
            int mo = w*16, c0 = k*8;
            float a0 = to_tf32(src[(mo + r    )*Cn + c0 + cq    ] * sc);
            float a1 = to_tf32(src[(mo + r + 8)*Cn + c0 + cq    ] * sc);
            float a2 = to_tf32(src[(mo + r    )*Cn + c0 + cq + 4] * sc);
            float a3 = to_tf32(src[(mo + r + 8)*Cn + c0 + cq + 4] * sc);
            g_wfrag[idx] = make_float4(a0, a1, a2, a3);
        }
        if (idx < CLn) g_ln2[idx] = make_float2(lng[idx], lnb[idx]);
        if (idx < Cn) g_bqs[idx] = bq[idx] * QSCALE;
    }
}

// ===== GEMM mainloop, 8 n-tiles (64 cols), pitch P (P mod 32 == 8 -> conflict-free) =====
#define GEMM_MMA8(WFp, XS, P)                                                   \
    int lane = tid & 31, w = tid >> 5;                                          \
    int r = lane >> 2, cq = lane & 3;                                           \
    float acc[8][4];                                                            \
    _Pragma("unroll")                                                           \
    for (int nt = 0; nt < 8; nt++){                                             \
        acc[nt][0] = 0.f; acc[nt][1] = 0.f; acc[nt][2] = 0.f; acc[nt][3] = 0.f; \
    }                                                                           \
    {                                                                           \
        const float4* af = (WFp) + w*512 + lane;                                \
        _Pragma("unroll")                                                       \
        for (int k = 0; k < 16; k++){                                           \
            float4 a = af[k*32];                                                \
            const float* xb = (XS) + (k*8 + cq)*(P) + r;                        \
            _Pragma("unroll")                                                   \
            for (int nt = 0; nt < 8; nt++){                                     \
                mma_tf32(acc[nt], a, xb[nt*8], xb[4*(P) + nt*8]);               \
            }                                                                   \
        }                                                                       \
    }

// ---------------- fused conv layer ----------------
// grid (B, NLT64), block 256
// smem: XsmH [c][70] pitch 72 (x halo; depthwise writes y[c][l] to index l+6 in-place)
#define CONV_SMEM_F (9216 + 1024 + 128 + 16)
__global__ __launch_bounds__(256, 4) void k_conv(
        const float* __restrict__ in, float* __restrict__ out,
        const float4* __restrict__ Wf,
        const float* __restrict__ dw, const float* __restrict__ db,
        const float* __restrict__ pb,
        const float* __restrict__ partIn, float* __restrict__ partOut, int nparts){
    extern __shared__ float sm[];
    float* XsmH = sm;                  // [c][70] pitch 72 ; y aliased at +6
    float* Dw   = sm + 9216;
    float* Db   = Dw + 1024;
    float* red  = Db + 128;
    int b = blockIdx.x, lt = blockIdx.y, tid = threadIdx.x;
    int l0 = lt * LT64;

    stats_from_parts(partIn, b, nparts, red);
    for (int idx = tid; idx < Cn*Kn; idx += 256)
        Dw[(idx/7)*8 + (idx - (idx/7)*7)] = dw[idx];
    if (tid < Cn) Db[tid] = db[tid];
    __syncthreads();
    float mu = red[0], rs = red[1];
    // main stage: 64 cols at row offset +3 (shift-based indexing, coalesced)
    #pragma unroll
    for (int k = 0; k < 32; k++){
        int idx = k*256 + tid;
        int c = idx >> 6, j = idx & 63;
        int gl = l0 + j;
        float v = 0.f;
        if (gl < Ln){
            float2 gb = g_ln2[c*Ln + gl];
            float a = rs*gb.x;
            v = fmaf(in[(b*Cn + c)*Ln + gl], a, fmaf(-mu, a, gb.y));
        }
        XsmH[c*72 + 3 + j] = v;
    }
    // halo stage: 6 cols per row (left 3 at offsets 0..2, right 3 at 67..69)
    #pragma unroll
    for (int k = 0; k < 3; k++){
        int idx = k*256 + tid;            // 0..767
        int c = idx & 127, h = idx >> 7;  // h 0..5
        int pos = (h < 3) ? h : (64 + h); // 0,1,2,67,68,69
        int gl = l0 - 3 + pos;
        float v = 0.f;
        if (gl >= 0 && gl < Ln){
            float2 gb = g_ln2[c*Ln + gl];
            float a = rs*gb.x;
            v = fmaf(in[(b*Cn + c)*Ln + gl], a, fmaf(-mu, a, gb.y));
        }
        XsmH[c*72 + pos] = v;
    }
    __syncthreads();
    // depthwise in-place: y[c][l] -> index l+6 (the x cell read in the same iteration)
    {
        int c  = tid >> 1;
        int lb = (tid & 1) * 32;
        float* xr = XsmH + c*72 + lb;
        float d0 = Dw[c*8+0], d1 = Dw[c*8+1], d2 = Dw[c*8+2], d3 = Dw[c*8+3];
        float d4 = Dw[c*8+4], d5 = Dw[c*8+5], d6 = Dw[c*8+6];
        float bias = Db[c];
        float w0 = xr[0], w1 = xr[1], w2 = xr[2], w3 = xr[3], w4 = xr[4], w5 = xr[5];
        __syncwarp();   // all preloads (x[lb..lb+5]) before any in-place writes
        #pragma unroll
        for (int l = 0; l < 32; l++){
            float w6 = xr[l + 6];
            float a = bias;
            a = fmaf(w0, d0, a); a = fmaf(w1, d1, a); a = fmaf(w2, d2, a);
            a = fmaf(w3, d3, a); a = fmaf(w4, d4, a); a = fmaf(w5, d5, a);
            a = fmaf(w6, d6, a);
            xr[l + 6] = to_tf32(a);          // overwrite the cell just read
            w0 = w1; w1 = w2; w2 = w3; w3 = w4; w4 = w5; w5 = w6;
        }
    }
    __syncthreads();

    GEMM_MMA8(Wf, XsmH + 6, 72)

    int mo = w*16;
    float s = 0.f, ss = 0.f;
    #pragma unroll
    for (int nt = 0; nt < 8; nt++){
        int col = l0 + nt*8 + 2*cq;
        if (col < Ln){
            int o1 = mo + r, o2 = o1 + 8;
            float b1v = pb[o1], b2v = pb[o2];
            float z0 = acc[nt][0] + b1v, z1 = acc[nt][1] + b1v;
            float z2 = acc[nt][2] + b2v, z3 = acc[nt][3] + b2v;
            z0 = z0 > 0.f ? z0 : 0.f;  z1 = z1 > 0.f ? z1 : 0.f;
            z2 = z2 > 0.f ? z2 : 0.f;  z3 = z3 > 0.f ? z3 : 0.f;
            float2 r1 = *(const float2*)&in[(b*Cn + o1)*Ln + col];
            float2 r2 = *(const float2*)&in[(b*Cn + o2)*Ln + col];
            float v0 = r1.x + z0, v1 = r1.y + z1;
            float v2 = r2.x + z2, v3 = r2.y + z3;
            *(float2*)&out[(b*Cn + o1)*Ln + col] = make_float2(v0, v1);
            *(float2*)&out[(b*Cn + o2)*Ln + col] = make_float2(v2, v3);
            s  += v0 + v1 + v2 + v3;
            ss += v0*v0 + v1*v1 + v2*v2 + v3*v3;
        }
    }
    block_reduce2(s, ss, &partOut[(b*64 + lt)*2], red);
}

// ---------------- generic matmul ----------------
// grid (B, NLT64), block 256
#define MM_SMEM_F (9216 + 16)
template<bool LN, bool RELU, bool STATS>
__global__ __launch_bounds__(256, 4) void k_mm(
        const float* __restrict__ in, const float* resid, float* __restrict__ out,
        const float4* __restrict__ Wf, const float* __restrict__ bias,
        const float* __restrict__ partIn, float* __restrict__ partOut, int nparts){
    extern __shared__ float sm[];
    float* Xsm = sm;                 // [c][64] pitch 72
    float* red = sm + 9216;
    int b = blockIdx.x, lt = blockIdx.y, tid = threadIdx.x;
    int l0 = lt * LT64;
    if (LN) stats_from_parts(partIn, b, nparts, red);
    __syncthreads();
    float mu = 0.f, rs = 1.f;
    if (LN){ mu = red[0]; rs = red[1]; }
    for (int idx = tid; idx < Cn*LT64; idx += 256){
        int c = idx >> 6, j = idx & 63;
        int gl = l0 + j;
        float v = 0.f;
        if (gl < Ln){
            v = in[(b*Cn + c)*Ln + gl];
            if (LN){
                float2 gb = g_ln2[c*Ln + gl];
                float a = rs*gb.x;
                v = fmaf(v, a, fmaf(-mu, a, gb.y));
            }
        }
        Xsm[c*72 + j] = to_tf32(v);
    }
    __syncthreads();

    GEMM_MMA8(Wf, Xsm, 72)

    int mo = w*16;
    float s = 0.f, ss = 0.f;
    #pragma unroll
    for (int nt = 0; nt < 8; nt++){
        int col = l0 + nt*8 + 2*cq;
        if (col < Ln){
            int o1 = mo + r, o2 = o1 + 8;
            float b1v = bias[o1], b2v = bias[o2];
            float z0 = acc[nt][0] + b1v, z1 = acc[nt][1] + b1v;
            float z2 = acc[nt][2] + b2v, z3 = acc[nt][3] + b2v;
            if (RELU){
                z0 = z0 > 0.f ? z0 : 0.f;  z1 = z1 > 0.f ? z1 : 0.f;
                z2 = z2 > 0.f ? z2 : 0.f;  z3 = z3 > 0.f ? z3 : 0.f;
            }
            float2 r1 = *(const float2*)&resid[(b*Cn + o1)*Ln + col];
            float2 r2 = *(const float2*)&resid[(b*Cn + o2)*Ln + col];
            float v0 = r1.x + z0, v1 = r1.y + z1;
            float v2 = r2.x + z2, v3 = r2.y + z3;
            *(float2*)&out[(b*Cn + o1)*Ln + col] = make_float2(v0, v1);
            *(float2*)&out[(b*Cn + o2)*Ln + col] = make_float2(v2, v3);
            if (STATS){
                s  += v0 + v1 + v2 + v3;
                ss += v0*v0 + v1*v1 + v2*v2 + v3*v3;
            }
        }
    }
    if (STATS) block_reduce2(s, ss, &partOut[(b*64 + lt)*2], red);
}

// ---------------- merged QKV: LT64, stage X once, 3 sequential A-streams ----------------
// grid (B, NLT64), block 256 ; X [c][64] pitch 72
#define QKV_SMEM_F (9216 + 16)
__global__ __launch_bounds__(256, 3) void k_qkv(
        const float* __restrict__ in,
        const float* __restrict__ bq_s, const float* __restrict__ bk,
        const float* __restrict__ bv,
        const float* __restrict__ partIn, int nparts){
    extern __shared__ float sm[];
    float* Xsm = sm;                 // [c][64] pitch 72
    float* red = sm + 9216;
    int b = blockIdx.x, lt = blockIdx.y, tid = threadIdx.x;
    int l0 = lt * LT64;
    stats_from_parts(partIn, b, nparts, red);
    __syncthreads();
    float mu = red[0], rs = red[1];
    for (int idx = tid; idx < Cn*LT64; idx += 256){
        int c = idx >> 6, j = idx & 63;
        int gl = l0 + j;
        float v = 0.f;
        if (gl < Ln){
            float2 gb = g_ln2[c*Ln + gl];
            float a = rs*gb.x;
            v = fmaf(in[(b*Cn + c)*Ln + gl], a, fmaf(-mu, a, gb.y));
        }
        Xsm[c*72 + j] = to_tf32(v);
    }
    __syncthreads();

    int lane = tid & 31, w = tid >> 5;
    int r = lane >> 2, cq = lane & 3;
    #pragma unroll
    for (int m = 0; m < 3; m++){
        const float4* af = g_wfrag + (4 + m)*4096 + w*512 + lane;
        float acc[8][4];
        #pragma unroll
        for (int nt = 0; nt < 8; nt++){
            acc[nt][0] = 0.f; acc[nt][1] = 0.f; acc[nt][2] = 0.f; acc[nt][3] = 0.f;
        }
        #pragma unroll
        for (int k = 0; k < 16; k++){
            float4 a = af[k*32];
            const float* xb = Xsm + (k*8 + cq)*72 + r;
            #pragma unroll
            for (int nt = 0; nt < 8; nt++){
                mma_tf32(acc[nt], a, xb[nt*8], xb[4*72 + nt*8]);
            }
        }
        const float* bias = (m == 0) ? bq_s : (m == 1) ? bk : bv;
        float* outp       = (m == 0) ? g_q  : (m == 1) ? g_k : g_v;
        int o1 = w*16 + r, o2 = o1 + 8;
        float b1v = bias[o1], b2v = bias[o2];
        #pragma unroll
        for (int nt = 0; nt < 8; nt++){
            int col = l0 + nt*8 + 2*cq;
            if (col < Ln){
                float* p = outp + ((size_t)(b*Hn + w)*Ln + col)*16;
                p[r]          = acc[nt][0] + b1v;
                p[16 + r]     = acc[nt][1] + b1v;
                p[r + 8]      = acc[nt][2] + b2v;
                p[16 + r + 8] = acc[nt][3] + b2v;
            }
        }
    }
}

// ---------------- attention: flash-style tf32 mma, shuffle P exchange ----------------
// smem = K(pitch20) + V(pitch24) + mask = 72 KB -> 3 blocks/SM
#define ATTN_K_P 20
#define ATTN_V_P 24
#define ATTN_SMEM_F (Ln*ATTN_K_P + Ln*ATTN_V_P + Ln)
__global__ __launch_bounds__(256, 3) void k_attn(const float* __restrict__ mask){
    extern __shared__ float sm[];
    float* Ksm = sm;                                  // pitch 20
    float* Vsm = sm + Ln*ATTN_K_P;                    // pitch 24
    float* Msm = Vsm + Ln*ATTN_V_P;
    int bh = blockIdx.x;
    int b = bh >> 3, h = bh & 7;
    int tid = threadIdx.x;
    {
        const float4* kp = (const float4*)(g_k + (size_t)bh*Ln*16);
        const float4* vp = (const float4*)(g_v + (size_t)bh*Ln*16);
        for (int i = tid; i < Ln*4; i += 256){
            int row = i >> 2, q = i & 3;
            float4 kv = kp[i];
            kv.x = to_tf32(kv.x); kv.y = to_tf32(kv.y);
            kv.z = to_tf32(kv.z); kv.w = to_tf32(kv.w);
            *(float4*)(Ksm + row*ATTN_K_P + q*4) = kv;
            float4 vv = vp[i];
            vv.x = to_tf32(vv.x); vv.y = to_tf32(vv.y);
            vv.z = to_tf32(vv.z); vv.w = to_tf32(vv.w);
            *(float4*)(Vsm + row*ATTN_V_P + q*4) = vv;
        }
        for (int i = tid; i < Ln; i += 256) Msm[i] = mask[b*Ln + i];
    }
    __syncthreads();

    int lane = tid & 31, w = tid >> 5;
    int r = lane >> 2, cq = lane & 3;
    int Lx = (lane & 28) | (cq >> 1);   // source lane for cols +cq
    int Lz = Lx + 2;                    // source lane for cols +cq+4
    bool odd = (cq & 1);
    const float* Qbase = g_q + (size_t)bh*Ln*16;
    size_t obase = ((size_t)b*Cn + h*16)*Ln;

    for (int mt = w; mt < 25; mt += 8){
        int mo = mt*16;
        float4 qf0, qf1;
        qf0.x = to_tf32(Qbase[(mo + r    )*16 + cq    ]);
        qf0.y = to_tf32(Qbase[(mo + r + 8)*16 + cq    ]);
        qf0.z = to_tf32(Qbase[(mo + r    )*16 + cq + 4]);
        qf0.w = to_tf32(Qbase[(mo + r + 8)*16 + cq + 4]);
        qf1.x = to_tf32(Qbase[(mo + r    )*16 + 8 + cq    ]);
        qf1.y = to_tf32(Qbase[(mo + r + 8)*16 + 8 + cq    ]);
        qf1.z = to_tf32(Qbase[(mo + r    )*16 + 8 + cq + 4]);
        qf1.w = to_tf32(Qbase[(mo + r + 8)*16 + 8 + cq + 4]);

        float m0 = -3.0e38f, m1 = -3.0e38f, den0 = 0.f, den1 = 0.f;
        float oa[2][4];
        oa[0][0]=oa[0][1]=oa[0][2]=oa[0][3]=0.f;
        oa[1][0]=oa[1][1]=oa[1][2]=oa[1][3]=0.f;

        for (int kc = 0; kc < Ln; kc += 40){
            float sc[5][4];
            #pragma unroll
            for (int st = 0; st < 5; st++){
                sc[st][0]=0.f; sc[st][1]=0.f; sc[st][2]=0.f; sc[st][3]=0.f;
                const float* kb = Ksm + (kc + st*8 + r)*ATTN_K_P + cq;
                mma_tf32(sc[st], qf0, kb[0], kb[4]);
                mma_tf32(sc[st], qf1, kb[8], kb[12]);
            }
            #pragma unroll
            for (int st = 0; st < 5; st++){
                float2 mk = *(const float2*)(Msm + kc + st*8 + 2*cq);
                float a0 = (1.f - mk.x)*(-1e30f), a1 = (1.f - mk.y)*(-1e30f);
                sc[st][0] = sc[st][0]*mk.x + a0;
                sc[st][1] = sc[st][1]*mk.y + a1;
                sc[st][2] = sc[st][2]*mk.x + a0;
                sc[st][3] = sc[st][3]*mk.y + a1;
            }
            float cm0 = -3.0e38f, cm1 = -3.0e38f;
            #pragma unroll
            for (int st = 0; st < 5; st++){
                cm0 = fmaxf(cm0, fmaxf(sc[st][0], sc[st][1]));
                cm1 = fmaxf(cm1, fmaxf(sc[st][2], sc[st][3]));
            }
            cm0 = fmaxf(cm0, __shfl_xor_sync(0xffffffffu, cm0, 1));
            cm0 = fmaxf(cm0, __shfl_xor_sync(0xffffffffu, cm0, 2));
            cm1 = fmaxf(cm1, __shfl_xor_sync(0xffffffffu, cm1, 1));
            cm1 = fmaxf(cm1, __shfl_xor_sync(0xffffffffu, cm1, 2));
            float nm0 = fmaxf(m0, cm0), nm1 = fmaxf(m1, cm1);
            float f0 = __expf(m0 - nm0), f1 = __expf(m1 - nm1);
            m0 = nm0; m1 = nm1;
            den0 *= f0; den1 *= f1;
            #pragma unroll
            for (int nt = 0; nt < 2; nt++){
                oa[nt][0] *= f0; oa[nt][1] *= f0;
                oa[nt][2] *= f1; oa[nt][3] *= f1;
            }
            // per 8-col chunk: p, den, C->A fragment via shuffles, PV mma
            #pragma unroll
            for (int st = 0; st < 5; st++){
                float p0 = __expf(sc[st][0] - m0);
                float p1 = __expf(sc[st][1] - m0);
                float p2 = __expf(sc[st][2] - m1);
                float p3 = __expf(sc[st][3] - m1);
                den0 += p0 + p1; den1 += p2 + p3;
                float t0 = to_tf32(p0), t1 = to_tf32(p1);
                float t2 = to_tf32(p2), t3 = to_tf32(p3);
                float e0 = __shfl_sync(0xffffffffu, t0, Lx);
                float e1 = __shfl_sync(0xffffffffu, t1, Lx);
                float f2v = __shfl_sync(0xffffffffu, t2, Lx);
                float f3v = __shfl_sync(0xffffffffu, t3, Lx);
                float g0 = __shfl_sync(0xffffffffu, t0, Lz);
                float g1 = __shfl_sync(0xffffffffu, t1, Lz);
                float h2 = __shfl_sync(0xffffffffu, t2, Lz);
                float h3 = __shfl_sync(0xffffffffu, t3, Lz);
                float4 a;
                a.x = odd ? e1  : e0;
                a.y = odd ? f3v : f2v;
                a.z = odd ? g1  : g0;
                a.w = odd ? h3  : h2;
                const float* vb  = Vsm + (kc + st*8 + cq    )*ATTN_V_P + r;
                const float* vb4 = Vsm + (kc + st*8 + cq + 4)*ATTN_V_P + r;
                mma_tf32(oa[0], a, vb[0], vb4[0]);
                mma_tf32(oa[1], a, vb[8], vb4[8]);
            }
        }
        den0 += __shfl_xor_sync(0xffffffffu, den0, 1);
        den0 += __shfl_xor_sync(0xffffffffu, den0, 2);
        den1 += __shfl_xor_sync(0xffffffffu, den1, 1);
        den1 += __shfl_xor_sync(0xffffffffu, den1, 2);
        float i0 = 1.f/den0, i1 = 1.f/den1;
        int row0 = mo + r, row1 = mo + r + 8;
        #pragma unroll
        for (int nt = 0; nt < 2; nt++){
            int d0 = nt*8 + 2*cq;
            g_scr[obase + (size_t)d0*Ln + row0]     = oa[nt][0]*i0;
            g_scr[obase + (size_t)(d0+1)*Ln + row0] = oa[nt][1]*i0;
            g_scr[obase + (size_t)d0*Ln + row1]     = oa[nt][2]*i1;
            g_scr[obase + (size_t)(d0+1)*Ln + row1] = oa[nt][3]*i1;
        }
    }
}

// ---------------- host launcher ----------------
extern "C" void kernel_launch(void* const* d_in, const int* in_sizes, int n_in,
                              void* d_out, int out_size){
    (void)in_sizes; (void)n_in; (void)out_size;
    const float* x    = (const float*)d_in[0];
    const float* mask = (const float*)d_in[1];
    const float* dw_w = (const float*)d_in[2];
    const float* dw_b = (const float*)d_in[3];
    const float* pw_w = (const float*)d_in[4];
    const float* pw_b = (const float*)d_in[5];
    const float* wq   = (const float*)d_in[6];
    const float* bq   = (const float*)d_in[7];
    const float* wk   = (const float*)d_in[8];
    const float* bk   = (const float*)d_in[9];
    const float* wv   = (const float*)d_in[10];
    const float* bv   = (const float*)d_in[11];
    const float* wo   = (const float*)d_in[12];
    const float* bo   = (const float*)d_in[13];
    const float* fc_w = (const float*)d_in[14];
    const float* fc_b = (const float*)d_in[15];
    const float* ln_g = (const float*)d_in[16];
    const float* ln_b = (const float*)d_in[17];
    float* outp = (float*)d_out;

    float *bufA, *bufB, *scr, *pA, *pB, *bqs;
    float4* wf;
    cudaGetSymbolAddress((void**)&bufA, g_bufA);
    cudaGetSymbolAddress((void**)&bufB, g_bufB);
    cudaGetSymbolAddress((void**)&scr,  g_scr);
    cudaGetSymbolAddress((void**)&pA,   g_partA);
    cudaGetSymbolAddress((void**)&pB,   g_partB);
    cudaGetSymbolAddress((void**)&wf,   g_wfrag);
    cudaGetSymbolAddress((void**)&bqs,  g_bqs);

    const int CONV_SMEM = CONV_SMEM_F * 4;
    const int MM_SMEM   = MM_SMEM_F * 4;
    const int QKV_SMEM  = QKV_SMEM_F * 4;
    const int ATTN_SMEM = ATTN_SMEM_F * 4;
    cudaFuncSetAttribute(k_attn, cudaFuncAttributeMaxDynamicSharedMemorySize, ATTN_SMEM);

    // stage 0+1: merged pos (+ prep duty on first 200 blocks), LN partials -> pA
    k_pos<<<dim3(Bn, 50), 256>>>(x, pw_w, wq, wk, wv, wo, fc_w, bq, ln_g, ln_b);

    // stage 2: 4 fused conv layers
    float* cin  = bufA;
    float* cout = bufB;
    const float* pin = pA;
    float* pout = pB;
    int nparts = 50;
    for (int i = 0; i < 4; i++){
        k_conv<<<dim3(Bn, NLT64), 256, CONV_SMEM>>>(cin, cout,
            wf + i*4096, dw_w + i*Cn*Kn, dw_b + i*Cn, pw_b + i*Cn,
            pin, pout, nparts);
        float* t = cin; cin = cout; cout = t;
        float* tp = (float*)pin; pin = pout; pout = tp;
        nparts = NLT64;
    }
    // cin = residual after 4 conv layers; partials in pin (nparts=7)

    // stage 3: attention
    k_qkv<<<dim3(Bn, NLT64), 256, QKV_SMEM>>>(cin, bqs, bk, bv, pin, nparts);
    k_attn<<<Bn*Hn, 256, ATTN_SMEM>>>(mask);
    k_mm<false,false,true><<<dim3(Bn, NLT64), 256, MM_SMEM>>>(scr, cin, cout,
        wf + 7*4096, bo, nullptr, pout, 0);

    // stage 4: FC + relu + residual -> final output
    k_mm<true,true,false><<<dim3(Bn, NLT64), 256, MM_SMEM>>>(cout, cout, outp,
        wf + 8*4096, fc_b, pout, nullptr, NLT64);
}